// round 9
// baseline (speedup 1.0000x reference)
#include <cuda_runtime.h>
#include <cuda_fp16.h>
#include <cstdint>

#define NN   1546
#define ND   1373
#define KF   1546
#define HEADS 8
#define EMAX 210000
#define EPSV 1e-12f
#define TAOV 0.4f

// ------------------- scratch (device globals; no allocs allowed) -------------------
__device__ __align__(16) float  g_fs  [NN * 512];
__device__ __align__(16) __half g_fs16[NN * 512];
__device__ __align__(16) float  g_res [NN * 512];
__device__ __align__(16) float  g_attn[NN * 512];
__device__ __align__(16) __half g_sn16[NN * 64];
__device__ __align__(16) __half g_tn16[NN * 64];
__device__ float g_snorm[NN];
__device__ float g_tnorm[NN];
__device__ float g_colsq [512];
__device__ float g_rscale[512];
__device__ int   g_cnt[NN];
__device__ int   g_off[NN];
__device__ int   g_cur[NN];
__device__ int   g_ssrc[EMAX];    // sorted: src | (efeat<<16)

// ------------------- helpers -------------------
__device__ __forceinline__ void mma_f16(float* c, const uint32_t* a, const uint32_t* b) {
    asm volatile(
        "mma.sync.aligned.m16n8k16.row.col.f32.f16.f16.f32 "
        "{%0,%1,%2,%3}, {%4,%5,%6,%7}, {%8,%9}, {%0,%1,%2,%3};\n"
        : "+f"(c[0]), "+f"(c[1]), "+f"(c[2]), "+f"(c[3])
        : "r"(a[0]), "r"(a[1]), "r"(a[2]), "r"(a[3]), "r"(b[0]), "r"(b[1]));
}

// ------------------- zero scratch counters -------------------
__global__ void k_zero() {
    int i = blockIdx.x * 256 + threadIdx.x;
    if (i < NN)  g_cnt[i] = 0;
    if (i < 512) g_colsq[i] = 0.f;
}

// ------------- fp16 GEMM: BM=128 BN=64 BK=32, 256 thr, 2 CTA/SM, warp tile 32x32 -------------
#define APADH 40   // halves per A row (32 used + 8 pad)
#define BPADH 40   // halves per B row (32 used + 8 pad), B transposed [n][k]

__device__ __forceinline__ void ldA3(const float* feat, int rowb, int rowEnd, int k0,
                                     int tid, float2* pa) {
#pragma unroll
    for (int j = 0; j < 8; j++) {
        int idx = tid + j * 256;           // 2048 float2 = 128 rows x 16
        int r = idx >> 4, c2 = idx & 15;
        int gr = rowb + r, gk = k0 + c2 * 2;
        float2 v = make_float2(0.f, 0.f);
        if (gr < rowEnd) {
            const float* p = feat + (size_t)gr * KF + gk;
            if (gk + 2 <= KF)      v = *(const float2*)p;
            else if (gk < KF)      v.x = *p;
        }
        pa[j] = v;
    }
}
__device__ __forceinline__ void ldB3(const float* W, int colb, int k0, int tid, float4* pb) {
#pragma unroll
    for (int j = 0; j < 2; j++) {
        int idx = tid + j * 256;           // 512 float4 = 32 rows x 16
        int r = idx >> 4, c4 = idx & 15;
        int gk = k0 + r;
        float4 v = make_float4(0.f, 0.f, 0.f, 0.f);
        if (gk < KF) v = *(const float4*)(W + (size_t)gk * 512 + colb + c4 * 4);
        pb[j] = v;
    }
}
__device__ __forceinline__ void stA3(__half* As, int tid, const float2* pa) {
#pragma unroll
    for (int j = 0; j < 8; j++) {
        int idx = tid + j * 256;
        int r = idx >> 4, c2 = idx & 15;
        *(half2*)(As + r * APADH + c2 * 2) = __floats2half2_rn(pa[j].x, pa[j].y);
    }
}
__device__ __forceinline__ void stB3(__half* Bs, int tid, const float4* pb) {
#pragma unroll
    for (int j = 0; j < 2; j++) {
        int idx = tid + j * 256;
        int r = idx >> 4, c4 = idx & 15;
        int n0 = c4 * 4;
        Bs[(n0 + 0) * BPADH + r] = __float2half_rn(pb[j].x);
        Bs[(n0 + 1) * BPADH + r] = __float2half_rn(pb[j].y);
        Bs[(n0 + 2) * BPADH + r] = __float2half_rn(pb[j].z);
        Bs[(n0 + 3) * BPADH + r] = __float2half_rn(pb[j].w);
    }
}

__global__ __launch_bounds__(256, 2) void k_gemm(const float* __restrict__ feat,
                                                 const float* __restrict__ Wp,
                                                 const float* __restrict__ Wr) {
    __shared__ __align__(16) __half As[2][128 * APADH];
    __shared__ __align__(16) __half Bs[2][64 * BPADH];
    int tid = threadIdx.x, lane = tid & 31, warp = tid >> 5;
    int by = blockIdx.y, bx = blockIdx.x;

    int g, rowb, rowEnd;
    if (by < 11) { g = 0; rowb = by * 128; rowEnd = ND; }
    else         { g = 1; rowb = ND + (by - 11) * 128; rowEnd = NN; }

    int cb0 = bx * 64;
    const float* W;
    float* outp;
    int colb;
    bool isFs;
    if (cb0 < 512) { W = Wp + (size_t)g * KF * 512; outp = g_fs;  colb = cb0;       isFs = true; }
    else           { W = Wr + (size_t)g * KF * 512; outp = g_res; colb = cb0 - 512; isFs = false; }

    float c[2][4][4];
#pragma unroll
    for (int i = 0; i < 2; i++)
#pragma unroll
        for (int j = 0; j < 4; j++)
#pragma unroll
            for (int k = 0; k < 4; k++) c[i][j][k] = 0.f;

    float2 pa[8];
    float4 pb[2];
    ldA3(feat, rowb, rowEnd, 0, tid, pa);
    ldB3(W, colb, 0, tid, pb);
    stA3(As[0], tid, pa);
    stB3(Bs[0], tid, pb);
    __syncthreads();

    int p = 0;
    int warpM = warp >> 1, warpN = warp & 1;
    int t2 = (lane & 3) * 2;
    for (int k0 = 0; k0 < KF; k0 += 32) {
        int kn = k0 + 32;
        if (kn < KF) { ldA3(feat, rowb, rowEnd, kn, tid, pa); ldB3(W, colb, kn, tid, pb); }

#pragma unroll
        for (int kk = 0; kk < 32; kk += 16) {
            uint32_t af[2][4], bf[4][2];
#pragma unroll
            for (int mt = 0; mt < 2; mt++) {
                int row = warpM * 32 + mt * 16 + (lane >> 2);
                af[mt][0] = *(const uint32_t*)&As[p][row * APADH + kk + t2];
                af[mt][1] = *(const uint32_t*)&As[p][(row + 8) * APADH + kk + t2];
                af[mt][2] = *(const uint32_t*)&As[p][row * APADH + kk + t2 + 8];
                af[mt][3] = *(const uint32_t*)&As[p][(row + 8) * APADH + kk + t2 + 8];
            }
#pragma unroll
            for (int nt = 0; nt < 4; nt++) {
                int col = warpN * 32 + nt * 8 + (lane >> 2);
                bf[nt][0] = *(const uint32_t*)&Bs[p][col * BPADH + kk + t2];
                bf[nt][1] = *(const uint32_t*)&Bs[p][col * BPADH + kk + t2 + 8];
            }
#pragma unroll
            for (int mt = 0; mt < 2; mt++)
#pragma unroll
                for (int nt = 0; nt < 4; nt++)
                    mma_f16(c[mt][nt], af[mt], bf[nt]);
        }

        if (kn < KF) {
            stA3(As[p ^ 1], tid, pa);
            stB3(Bs[p ^ 1], tid, pb);
            __syncthreads();
            p ^= 1;
        }
    }

#pragma unroll
    for (int mt = 0; mt < 2; mt++) {
        int row0 = rowb + warpM * 32 + mt * 16 + (lane >> 2);
#pragma unroll
        for (int nt = 0; nt < 4; nt++) {
            int col = colb + warpN * 32 + nt * 8 + (lane & 3) * 2;
            if (row0 < rowEnd) {
                *(float2*)(outp + (size_t)row0 * 512 + col) = make_float2(c[mt][nt][0], c[mt][nt][1]);
                if (isFs)
                    *(half2*)(g_fs16 + (size_t)row0 * 512 + col) = __floats2half2_rn(c[mt][nt][0], c[mt][nt][1]);
            }
            if (row0 + 8 < rowEnd) {
                *(float2*)(outp + (size_t)(row0 + 8) * 512 + col) = make_float2(c[mt][nt][2], c[mt][nt][3]);
                if (isFs)
                    *(half2*)(g_fs16 + (size_t)(row0 + 8) * 512 + col) = __floats2half2_rn(c[mt][nt][2], c[mt][nt][3]);
            }
        }
    }
}

// ------------------- ft_attn + column sq-sums (fused) -------------------
#define ATTN_CH 194
__global__ __launch_bounds__(256) void k_attn(const float* __restrict__ Wprob) {
    __shared__ float Wh[4096];
    __shared__ float fsh[8][64];
    __shared__ float s_csq[64];
    int tid = threadIdx.x, warp = tid >> 5, lane = tid & 31;
    int h = blockIdx.x & 7, chunk = blockIdx.x >> 3;
    const float* W = Wprob + h * 4096;
    for (int i = tid; i < 4096; i += 256) Wh[i] = W[i];
    if (tid < 64) s_csq[tid] = 0.f;
    __syncthreads();

    float sq0 = 0.f, sq1 = 0.f;
    int n0 = chunk * ATTN_CH;
    int n1 = min(n0 + ATTN_CH, NN);
    for (int n = n0 + warp; n < n1; n += 8) {
        float v0 = g_fs[n * 512 + h * 64 + lane];
        float v1 = g_fs[n * 512 + h * 64 + lane + 32];
        fsh[warp][lane]      = v0;
        fsh[warp][lane + 32] = v1;
        sq0 += v0 * v0;
        sq1 += v1 * v1;
        __syncwarp();
        float a0 = 0.f, a1 = 0.f;
#pragma unroll 8
        for (int d = 0; d < 64; d++) {
            float f = fsh[warp][d];
            a0 += f * Wh[d * 64 + lane];
            a1 += f * Wh[d * 64 + lane + 32];
        }
        float t0 = tanhf(a0), t1 = tanhf(a1);
        float m = fmaxf(t0, t1);
#pragma unroll
        for (int off = 16; off; off >>= 1) m = fmaxf(m, __shfl_xor_sync(0xffffffffu, m, off));
        float e0 = __expf(t0 - m), e1 = __expf(t1 - m);
        float s = e0 + e1;
#pragma unroll
        for (int off = 16; off; off >>= 1) s += __shfl_xor_sync(0xffffffffu, s, off);
        float inv = 1.f / s;
        g_attn[n * 512 + h * 64 + lane]      = e0 * inv;
        g_attn[n * 512 + h * 64 + lane + 32] = e1 * inv;
        __syncwarp();
    }
    atomicAdd(&s_csq[lane], sq0);
    atomicAdd(&s_csq[lane + 32], sq1);
    __syncthreads();
    if (tid < 64) atomicAdd(&g_colsq[h * 64 + tid], s_csq[tid]);
}

// ------------------- row norms of sloc / topo -> normalized fp16 + norms -------------------
__global__ __launch_bounds__(128) void k_rownorm(const float* __restrict__ sloc,
                                                 const float* __restrict__ topo) {
    int warp = threadIdx.x >> 5, lane = threadIdx.x & 31;
    int n = blockIdx.x * 4 + warp;
    if (n >= NN) return;
    float2 sv = *(const float2*)(sloc + (size_t)n * 64 + 2 * lane);
    float2 tv = *(const float2*)(topo + (size_t)n * 64 + 2 * lane);
    float ss = sv.x * sv.x + sv.y * sv.y;
    float tt = tv.x * tv.x + tv.y * tv.y;
#pragma unroll
    for (int off = 16; off; off >>= 1) {
        ss += __shfl_xor_sync(0xffffffffu, ss, off);
        tt += __shfl_xor_sync(0xffffffffu, tt, off);
    }
    float sn = fmaxf(sqrtf(ss), EPSV), tn = fmaxf(sqrtf(tt), EPSV);
    float si = 1.f / sn, ti = 1.f / tn;
    ((half2*)(g_sn16 + (size_t)n * 64))[lane] = __floats2half2_rn(sv.x * si, sv.y * si);
    ((half2*)(g_tn16 + (size_t)n * 64))[lane] = __floats2half2_rn(tv.x * ti, tv.y * ti);
    if (lane == 0) { g_snorm[n] = sn; g_tnorm[n] = tn; }
}

// ------------------- counting sort of edges by dst -------------------
__global__ void k_hist(const int* __restrict__ dst, int E) {
    int e = blockIdx.x * 256 + threadIdx.x;
    if (e < E) atomicAdd(&g_cnt[dst[e]], 1);
}
__global__ __launch_bounds__(512) void k_scan() {
    __shared__ int sh[512];
    int t = threadIdx.x;
    int base = t * 4;
    int v0 = (base     < NN) ? g_cnt[base]     : 0;
    int v1 = (base + 1 < NN) ? g_cnt[base + 1] : 0;
    int v2 = (base + 2 < NN) ? g_cnt[base + 2] : 0;
    int v3 = (base + 3 < NN) ? g_cnt[base + 3] : 0;
    int p0 = v0, p1 = p0 + v1, p2 = p1 + v2, p3 = p2 + v3;
    sh[t] = p3;
    __syncthreads();
    for (int off = 1; off < 512; off <<= 1) {
        int x = 0;
        if (t >= off) x = sh[t - off];
        __syncthreads();
        sh[t] += x;
        __syncthreads();
    }
    int excl = sh[t] - p3;
    if (base     < NN) { g_off[base]     = excl;      g_cur[base]     = excl; }
    if (base + 1 < NN) { g_off[base + 1] = excl + p0; g_cur[base + 1] = excl + p0; }
    if (base + 2 < NN) { g_off[base + 2] = excl + p1; g_cur[base + 2] = excl + p1; }
    if (base + 3 < NN) { g_off[base + 3] = excl + p2; g_cur[base + 3] = excl + p2; }
    g_rscale[t] = 1.f / fmaxf(sqrtf(g_colsq[t]), EPSV);
}
__global__ void k_scatter(const int* __restrict__ dst, const int* __restrict__ src,
                          const int* __restrict__ efeat, int E) {
    int e = blockIdx.x * 256 + threadIdx.x;
    if (e < E) {
        int pos = atomicAdd(&g_cur[dst[e]], 1);
        g_ssrc[pos] = src[e] | (efeat[e] << 16);
    }
}

// ------------------- edge phase: single pass, online softmax, short dep chain -------------------
__global__ __launch_bounds__(256, 2) void k_edge(const float* __restrict__ sloc,
                                                 const float* __restrict__ topo,
                                                 const float* __restrict__ etw_tab,
                                                 float* __restrict__ out) {
    __shared__ float s_as[512];
    __shared__ float s_sd[64], s_td[64];
    __shared__ float s_accR[512], s_accS[512], s_accT[512];
    __shared__ float s_gmax[8], s_den[8], s_wmax[64], s_etw[4];

    int n = blockIdx.x;
    int tid = threadIdx.x, warp = tid >> 5, lane = tid & 31;
    int start = g_off[n], cnt = g_cnt[n];

    for (int i = tid; i < 512; i += 256) {
        s_as[i] = g_attn[n * 512 + i] * g_rscale[i];
        s_accR[i] = 0.f; s_accS[i] = 0.f; s_accT[i] = 0.f;
    }
    if (tid < 64) {
        s_sd[tid] = __half2float(g_sn16[n * 64 + tid]);
        s_td[tid] = __half2float(g_tn16[n * 64 + tid]);
    }
    if (tid < 8) s_den[tid] = 0.f;
    if (tid < 4) s_etw[tid] = etw_tab[tid];
    __syncthreads();

    int h = lane >> 2, q = lane & 3;
    int kb = lane * 16, d0 = q * 16;
    float m = -1e30f, dsum = 0.f;
    float accR[16], accS[16], accT[16];
#pragma unroll
    for (int k = 0; k < 16; k++) { accR[k] = 0.f; accS[k] = 0.f; accT[k] = 0.f; }

    for (int i = warp; i < cnt; i += 8) {
        int packed = g_ssrc[start + i];
        int s = packed & 0xFFFF;
        float etw = s_etw[packed >> 16];

        const int4* fp = (const int4*)(g_fs16 + (size_t)s * 512 + kb);
        int4 fA = fp[0], fB = fp[1];
        const int4* sp = (const int4*)(g_sn16 + (size_t)s * 64 + d0);
        int4 s0 = sp[0], s1 = sp[1];
        const int4* tp = (const int4*)(g_tn16 + (size_t)s * 64 + d0);
        int4 t0 = tp[0], t1 = tp[1];
        float snm = g_snorm[s], tnm = g_tnorm[s];

        const half2* h2a = (const half2*)&fA;
        const half2* h2b = (const half2*)&fB;
        const half2* sh0 = (const half2*)&s0; const half2* sh1 = (const half2*)&s1;
        const half2* th0 = (const half2*)&t0; const half2* th1 = (const half2*)&t1;

        float a = 0.f, cs = 0.f, ct = 0.f;
#pragma unroll
        for (int j = 0; j < 4; j++) {
            float2 f0 = __half22float2(h2a[j]);
            float2 f1 = __half22float2(h2b[j]);
            a += f0.x * s_as[kb + 2 * j]     + f0.y * s_as[kb + 2 * j + 1];
            a += f1.x * s_as[kb + 8 + 2 * j] + f1.y * s_as[kb + 8 + 2 * j + 1];
            float2 v0 = __half22float2(sh0[j]);
            float2 v1 = __half22float2(sh1[j]);
            cs += v0.x * s_sd[d0 + 2 * j]     + v0.y * s_sd[d0 + 2 * j + 1];
            cs += v1.x * s_sd[d0 + 8 + 2 * j] + v1.y * s_sd[d0 + 8 + 2 * j + 1];
            float2 w0 = __half22float2(th0[j]);
            float2 w1 = __half22float2(th1[j]);
            ct += w0.x * s_td[d0 + 2 * j]     + w0.y * s_td[d0 + 2 * j + 1];
            ct += w1.x * s_td[d0 + 8 + 2 * j] + w1.y * s_td[d0 + 8 + 2 * j + 1];
        }
        a  += __shfl_xor_sync(0xffffffffu, a, 1);
        cs += __shfl_xor_sync(0xffffffffu, cs, 1);
        ct += __shfl_xor_sync(0xffffffffu, ct, 1);
        a  += __shfl_xor_sync(0xffffffffu, a, 2);
        cs += __shfl_xor_sync(0xffffffffu, cs, 2);
        ct += __shfl_xor_sync(0xffffffffu, ct, 2);

        float sim = (TAOV * cs + (1.f - TAOV) * ct + 1.f) * 0.5f;
        float ev = sim * a * etw;

        float mnew = fmaxf(m, ev);
        float ex = __expf(ev - mnew);
        if (ev > m) {
            float so = __expf(m - mnew);
            dsum *= so;
#pragma unroll
            for (int k = 0; k < 16; k++) { accR[k] *= so; accS[k] *= so; accT[k] *= so; }
            m = mnew;
        }
        dsum += ex;

        float exs = ex * snm, ext = ex * tnm;
#pragma unroll
        for (int j = 0; j < 4; j++) {
            float2 f0 = __half22float2(h2a[j]);
            accR[2 * j]     += ex * f0.x;
            accR[2 * j + 1] += ex * f0.y;
            float2 f1 = __half22float2(h2b[j]);
            accR[8 + 2 * j]     += ex * f1.x;
            accR[8 + 2 * j + 1] += ex * f1.y;
            float2 v0 = __half22float2(sh0[j]);
            accS[2 * j]     += exs * v0.x;
            accS[2 * j + 1] += exs * v0.y;
            float2 v1 = __half22float2(sh1[j]);
            accS[8 + 2 * j]     += exs * v1.x;
            accS[8 + 2 * j + 1] += exs * v1.y;
            float2 w0 = __half22float2(th0[j]);
            accT[2 * j]     += ext * w0.x;
            accT[2 * j + 1] += ext * w0.y;
            float2 w1 = __half22float2(th1[j]);
            accT[8 + 2 * j]     += ext * w1.x;
            accT[8 + 2 * j + 1] += ext * w1.y;
        }
    }

    if (q == 0) s_wmax[warp * 8 + h] = m;
    __syncthreads();
    if (tid < 8) {
        float mm = -1e30f;
#pragma unroll
        for (int w = 0; w < 8; w++) mm = fmaxf(mm, s_wmax[w * 8 + tid]);
        s_gmax[tid] = mm;
    }
    __syncthreads();
    float sc = __expf(m - s_gmax[h]);
    if (q == 0) atomicAdd(&s_den[h], dsum * sc);
#pragma unroll
    for (int k = 0; k < 16; k++) {
        atomicAdd(&s_accR[kb + k], accR[k] * sc);
        atomicAdd(&s_accS[kb + k], accS[k] * sc);
        atomicAdd(&s_accT[kb + k], accT[k] * sc);
    }
    __syncthreads();

    if (tid < 64) {
        int d = tid;
        float rsum = 0.f, ssum = 0.f, tsum = 0.f;
#pragma unroll
        for (int hh = 0; hh < 8; hh++) {
            float den = s_den[hh];
            float inv = (den > 0.f) ? (1.f / den) : 0.f;
            float r = s_accR[hh * 64 + d] * inv + g_res[n * 512 + hh * 64 + d];
            rsum += fmaxf(r, 0.f);
            ssum += s_accS[hh * 64 + d] * inv;
            tsum += s_accT[hh * 64 + d] * inv;
        }
        out[n * 64 + d]               = rsum * 0.125f;
        out[NN * 64 + n * 64 + d]     = sloc[n * 64 + d] + ssum * 0.125f;
        out[2 * NN * 64 + n * 64 + d] = topo[n * 64 + d] + tsum * 0.125f;
    }
}

// ------------------- launch (k_gemm kept in profile slot 4) -------------------
extern "C" void kernel_launch(void* const* d_in, const int* in_sizes, int n_in,
                              void* d_out, int out_size) {
    const float* feat  = (const float*)d_in[0];
    const float* sloc  = (const float*)d_in[1];
    const float* topo  = (const float*)d_in[2];
    const float* Wp    = (const float*)d_in[3];
    const float* Wr    = (const float*)d_in[4];
    const float* Wprob = (const float*)d_in[5];
    const float* etw   = (const float*)d_in[6];
    const int*   src   = (const int*)d_in[7];
    const int*   dst   = (const int*)d_in[8];
    const int*   ef    = (const int*)d_in[9];
    float* out = (float*)d_out;
    int E = in_sizes[7];
    if (E > EMAX) E = EMAX;

    k_zero<<<7, 256>>>();                                   // 1
    k_hist<<<(E + 255) / 256, 256>>>(dst, E);               // 2
    k_rownorm<<<(NN + 3) / 4, 128>>>(sloc, topo);           // 3
    k_gemm<<<dim3(16, 13), 256>>>(feat, Wp, Wr);            // 4  <- ncu target
    k_attn<<<64, 256>>>(Wprob);                             // 5
    k_scan<<<1, 512>>>();                                   // 6
    k_scatter<<<(E + 255) / 256, 256>>>(dst, src, ef, E);   // 7
    k_edge<<<NN, 256>>>(sloc, topo, etw, out);              // 8
}

// round 10
// speedup vs baseline: 1.0056x; 1.0056x over previous
#include <cuda_runtime.h>
#include <cuda_fp16.h>
#include <cstdint>

#define NN   1546
#define ND   1373
#define KF   1546
#define HEADS 8
#define EMAX 210000
#define EPSV 1e-12f
#define TAOV 0.4f

// ------------------- scratch (device globals; no allocs allowed) -------------------
__device__ __align__(16) float  g_fs  [NN * 512];
__device__ __align__(16) __half g_fs16[NN * 512];
__device__ __align__(16) float  g_res [NN * 512];
__device__ __align__(16) float  g_attn[NN * 512];
__device__ __align__(16) __half g_sn16[NN * 64];
__device__ __align__(16) __half g_tn16[NN * 64];
__device__ float g_snorm[NN];
__device__ float g_tnorm[NN];
__device__ float g_colsq [512];
__device__ float g_rscale[512];
__device__ int   g_cnt[NN];
__device__ int   g_off[NN];
__device__ int   g_cur[NN];
__device__ int   g_ssrc[EMAX];    // sorted: src | (efeat<<16)

// ------------------- helpers -------------------
__device__ __forceinline__ void mma_f16(float* c, const uint32_t* a, const uint32_t* b) {
    asm volatile(
        "mma.sync.aligned.m16n8k16.row.col.f32.f16.f16.f32 "
        "{%0,%1,%2,%3}, {%4,%5,%6,%7}, {%8,%9}, {%0,%1,%2,%3};\n"
        : "+f"(c[0]), "+f"(c[1]), "+f"(c[2]), "+f"(c[3])
        : "r"(a[0]), "r"(a[1]), "r"(a[2]), "r"(a[3]), "r"(b[0]), "r"(b[1]));
}
__device__ __forceinline__ void ldmx4(uint32_t& r0, uint32_t& r1, uint32_t& r2, uint32_t& r3,
                                      uint32_t addr) {
    asm volatile("ldmatrix.sync.aligned.m8n8.x4.shared.b16 {%0,%1,%2,%3}, [%4];"
                 : "=r"(r0), "=r"(r1), "=r"(r2), "=r"(r3) : "r"(addr));
}

// ------------------- zero scratch counters -------------------
__global__ void k_zero() {
    int i = blockIdx.x * 256 + threadIdx.x;
    if (i < NN)  g_cnt[i] = 0;
    if (i < 512) g_colsq[i] = 0.f;
}

// ------------- fp16 GEMM: BM=128 BN=64 BK=32, 256 thr, 2 CTA/SM, ldmatrix fragments -------------
#define APADH 40   // halves per A row (32 used + 8 pad) -> 80B stride, conflict-free ldmatrix
#define BPADH 40

__device__ __forceinline__ void ldA3(const float* feat, int rowb, int rowEnd, int k0,
                                     int tid, float2* pa) {
#pragma unroll
    for (int j = 0; j < 8; j++) {
        int idx = tid + j * 256;
        int r = idx >> 4, c2 = idx & 15;
        int gr = rowb + r, gk = k0 + c2 * 2;
        float2 v = make_float2(0.f, 0.f);
        if (gr < rowEnd) {
            const float* p = feat + (size_t)gr * KF + gk;
            if (gk + 2 <= KF)      v = *(const float2*)p;
            else if (gk < KF)      v.x = *p;
        }
        pa[j] = v;
    }
}
__device__ __forceinline__ void ldB3(const float* W, int colb, int k0, int tid, float4* pb) {
#pragma unroll
    for (int j = 0; j < 2; j++) {
        int idx = tid + j * 256;
        int r = idx >> 4, c4 = idx & 15;
        int gk = k0 + r;
        float4 v = make_float4(0.f, 0.f, 0.f, 0.f);
        if (gk < KF) v = *(const float4*)(W + (size_t)gk * 512 + colb + c4 * 4);
        pb[j] = v;
    }
}
__device__ __forceinline__ void stA3(__half* As, int tid, const float2* pa) {
#pragma unroll
    for (int j = 0; j < 8; j++) {
        int idx = tid + j * 256;
        int r = idx >> 4, c2 = idx & 15;
        *(half2*)(As + r * APADH + c2 * 2) = __floats2half2_rn(pa[j].x, pa[j].y);
    }
}
__device__ __forceinline__ void stB3(__half* Bs, int tid, const float4* pb) {
#pragma unroll
    for (int j = 0; j < 2; j++) {
        int idx = tid + j * 256;
        int r = idx >> 4, c4 = idx & 15;
        int n0 = c4 * 4;
        Bs[(n0 + 0) * BPADH + r] = __float2half_rn(pb[j].x);
        Bs[(n0 + 1) * BPADH + r] = __float2half_rn(pb[j].y);
        Bs[(n0 + 2) * BPADH + r] = __float2half_rn(pb[j].z);
        Bs[(n0 + 3) * BPADH + r] = __float2half_rn(pb[j].w);
    }
}

__global__ __launch_bounds__(256, 2) void k_gemm(const float* __restrict__ feat,
                                                 const float* __restrict__ Wp,
                                                 const float* __restrict__ Wr) {
    __shared__ __align__(16) __half As[2][128 * APADH];
    __shared__ __align__(16) __half Bs[2][64 * BPADH];
    int tid = threadIdx.x, lane = tid & 31, warp = tid >> 5;
    int by = blockIdx.y, bx = blockIdx.x;

    int g, rowb, rowEnd;
    if (by < 11) { g = 0; rowb = by * 128; rowEnd = ND; }
    else         { g = 1; rowb = ND + (by - 11) * 128; rowEnd = NN; }

    int cb0 = bx * 64;
    const float* W;
    float* outp;
    int colb;
    bool isFs;
    if (cb0 < 512) { W = Wp + (size_t)g * KF * 512; outp = g_fs;  colb = cb0;       isFs = true; }
    else           { W = Wr + (size_t)g * KF * 512; outp = g_res; colb = cb0 - 512; isFs = false; }

    float c[2][4][4];
#pragma unroll
    for (int i = 0; i < 2; i++)
#pragma unroll
        for (int j = 0; j < 4; j++)
#pragma unroll
            for (int k = 0; k < 4; k++) c[i][j][k] = 0.f;

    float2 pa[8];
    float4 pb[2];
    ldA3(feat, rowb, rowEnd, 0, tid, pa);
    ldB3(W, colb, 0, tid, pb);
    stA3(As[0], tid, pa);
    stB3(Bs[0], tid, pb);
    __syncthreads();

    int p = 0;
    int warpM = warp >> 1, warpN = warp & 1;
    int l8 = lane & 7, grp = lane >> 3;
    // ldmatrix lane->address components (constant over the K loop)
    int aRowOff = warpM * 32 + ((grp & 1) << 3) + l8;   // + mt*16
    int aKOff   = (grp >> 1) << 3;                      // + kk
    int bNOff   = warpN * 32 + ((grp >> 1) << 3) + l8;  // + pair*16
    int bKOff   = (grp & 1) << 3;                       // + kk

    for (int k0 = 0; k0 < KF; k0 += 32) {
        int kn = k0 + 32;
        if (kn < KF) { ldA3(feat, rowb, rowEnd, kn, tid, pa); ldB3(W, colb, kn, tid, pb); }

        uint32_t a_base = (uint32_t)__cvta_generic_to_shared(&As[p][0]);
        uint32_t b_base = (uint32_t)__cvta_generic_to_shared(&Bs[p][0]);
#pragma unroll
        for (int kk = 0; kk < 32; kk += 16) {
            uint32_t af[2][4], bf[4][2];
#pragma unroll
            for (int mt = 0; mt < 2; mt++) {
                uint32_t addr = a_base + (uint32_t)(((aRowOff + mt * 16) * APADH + kk + aKOff) * 2);
                ldmx4(af[mt][0], af[mt][1], af[mt][2], af[mt][3], addr);
            }
#pragma unroll
            for (int pr = 0; pr < 2; pr++) {
                uint32_t addr = b_base + (uint32_t)(((bNOff + pr * 16) * BPADH + kk + bKOff) * 2);
                ldmx4(bf[2 * pr][0], bf[2 * pr][1], bf[2 * pr + 1][0], bf[2 * pr + 1][1], addr);
            }
#pragma unroll
            for (int mt = 0; mt < 2; mt++)
#pragma unroll
                for (int nt = 0; nt < 4; nt++)
                    mma_f16(c[mt][nt], af[mt], bf[nt]);
        }

        if (kn < KF) {
            stA3(As[p ^ 1], tid, pa);
            stB3(Bs[p ^ 1], tid, pb);
            __syncthreads();
            p ^= 1;
        }
    }

#pragma unroll
    for (int mt = 0; mt < 2; mt++) {
        int row0 = rowb + warpM * 32 + mt * 16 + (lane >> 2);
#pragma unroll
        for (int nt = 0; nt < 4; nt++) {
            int col = colb + warpN * 32 + nt * 8 + (lane & 3) * 2;
            if (row0 < rowEnd) {
                *(float2*)(outp + (size_t)row0 * 512 + col) = make_float2(c[mt][nt][0], c[mt][nt][1]);
                if (isFs)
                    *(half2*)(g_fs16 + (size_t)row0 * 512 + col) = __floats2half2_rn(c[mt][nt][0], c[mt][nt][1]);
            }
            if (row0 + 8 < rowEnd) {
                *(float2*)(outp + (size_t)(row0 + 8) * 512 + col) = make_float2(c[mt][nt][2], c[mt][nt][3]);
                if (isFs)
                    *(half2*)(g_fs16 + (size_t)(row0 + 8) * 512 + col) = __floats2half2_rn(c[mt][nt][2], c[mt][nt][3]);
            }
        }
    }
}

// ------------------- ft_attn + column sq-sums (fused), 128 blocks -------------------
#define ATTN_CH 97
__global__ __launch_bounds__(256) void k_attn(const float* __restrict__ Wprob) {
    __shared__ float Wh[4096];
    __shared__ float fsh[8][64];
    __shared__ float s_csq[64];
    int tid = threadIdx.x, warp = tid >> 5, lane = tid & 31;
    int h = blockIdx.x & 7, chunk = blockIdx.x >> 3;
    const float* W = Wprob + h * 4096;
    for (int i = tid; i < 4096; i += 256) Wh[i] = W[i];
    if (tid < 64) s_csq[tid] = 0.f;
    __syncthreads();

    float sq0 = 0.f, sq1 = 0.f;
    int n0 = chunk * ATTN_CH;
    int n1 = min(n0 + ATTN_CH, NN);
    for (int n = n0 + warp; n < n1; n += 8) {
        float v0 = g_fs[n * 512 + h * 64 + lane];
        float v1 = g_fs[n * 512 + h * 64 + lane + 32];
        fsh[warp][lane]      = v0;
        fsh[warp][lane + 32] = v1;
        sq0 += v0 * v0;
        sq1 += v1 * v1;
        __syncwarp();
        float a0 = 0.f, a1 = 0.f;
#pragma unroll 8
        for (int d = 0; d < 64; d++) {
            float f = fsh[warp][d];
            a0 += f * Wh[d * 64 + lane];
            a1 += f * Wh[d * 64 + lane + 32];
        }
        float t0 = tanhf(a0), t1 = tanhf(a1);
        float m = fmaxf(t0, t1);
#pragma unroll
        for (int off = 16; off; off >>= 1) m = fmaxf(m, __shfl_xor_sync(0xffffffffu, m, off));
        float e0 = __expf(t0 - m), e1 = __expf(t1 - m);
        float s = e0 + e1;
#pragma unroll
        for (int off = 16; off; off >>= 1) s += __shfl_xor_sync(0xffffffffu, s, off);
        float inv = 1.f / s;
        g_attn[n * 512 + h * 64 + lane]      = e0 * inv;
        g_attn[n * 512 + h * 64 + lane + 32] = e1 * inv;
        __syncwarp();
    }
    atomicAdd(&s_csq[lane], sq0);
    atomicAdd(&s_csq[lane + 32], sq1);
    __syncthreads();
    if (tid < 64) atomicAdd(&g_colsq[h * 64 + tid], s_csq[tid]);
}

// ------------------- row norms of sloc / topo -------------------
__global__ __launch_bounds__(128) void k_rownorm(const float* __restrict__ sloc,
                                                 const float* __restrict__ topo) {
    int warp = threadIdx.x >> 5, lane = threadIdx.x & 31;
    int n = blockIdx.x * 4 + warp;
    if (n >= NN) return;
    float2 sv = *(const float2*)(sloc + (size_t)n * 64 + 2 * lane);
    float2 tv = *(const float2*)(topo + (size_t)n * 64 + 2 * lane);
    float ss = sv.x * sv.x + sv.y * sv.y;
    float tt = tv.x * tv.x + tv.y * tv.y;
#pragma unroll
    for (int off = 16; off; off >>= 1) {
        ss += __shfl_xor_sync(0xffffffffu, ss, off);
        tt += __shfl_xor_sync(0xffffffffu, tt, off);
    }
    float sn = fmaxf(sqrtf(ss), EPSV), tn = fmaxf(sqrtf(tt), EPSV);
    float si = 1.f / sn, ti = 1.f / tn;
    ((half2*)(g_sn16 + (size_t)n * 64))[lane] = __floats2half2_rn(sv.x * si, sv.y * si);
    ((half2*)(g_tn16 + (size_t)n * 64))[lane] = __floats2half2_rn(tv.x * ti, tv.y * ti);
    if (lane == 0) { g_snorm[n] = sn; g_tnorm[n] = tn; }
}

// ------------------- counting sort of edges by dst -------------------
__global__ void k_hist(const int* __restrict__ dst, int E) {
    int e = blockIdx.x * 256 + threadIdx.x;
    if (e < E) atomicAdd(&g_cnt[dst[e]], 1);
}
__global__ __launch_bounds__(512) void k_scan() {
    __shared__ int sh[512];
    int t = threadIdx.x;
    int base = t * 4;
    int v0 = (base     < NN) ? g_cnt[base]     : 0;
    int v1 = (base + 1 < NN) ? g_cnt[base + 1] : 0;
    int v2 = (base + 2 < NN) ? g_cnt[base + 2] : 0;
    int v3 = (base + 3 < NN) ? g_cnt[base + 3] : 0;
    int p0 = v0, p1 = p0 + v1, p2 = p1 + v2, p3 = p2 + v3;
    sh[t] = p3;
    __syncthreads();
    for (int off = 1; off < 512; off <<= 1) {
        int x = 0;
        if (t >= off) x = sh[t - off];
        __syncthreads();
        sh[t] += x;
        __syncthreads();
    }
    int excl = sh[t] - p3;
    if (base     < NN) { g_off[base]     = excl;      g_cur[base]     = excl; }
    if (base + 1 < NN) { g_off[base + 1] = excl + p0; g_cur[base + 1] = excl + p0; }
    if (base + 2 < NN) { g_off[base + 2] = excl + p1; g_cur[base + 2] = excl + p1; }
    if (base + 3 < NN) { g_off[base + 3] = excl + p2; g_cur[base + 3] = excl + p2; }
    g_rscale[t] = 1.f / fmaxf(sqrtf(g_colsq[t]), EPSV);
}
__global__ void k_scatter(const int* __restrict__ dst, const int* __restrict__ src,
                          const int* __restrict__ efeat, int E) {
    int e = blockIdx.x * 256 + threadIdx.x;
    if (e < E) {
        int pos = atomicAdd(&g_cur[dst[e]], 1);
        g_ssrc[pos] = src[e] | (efeat[e] << 16);
    }
}

// ------------------- edge phase: online softmax, prefetched gathers -------------------
__global__ __launch_bounds__(256, 2) void k_edge(const float* __restrict__ sloc,
                                                 const float* __restrict__ topo,
                                                 const float* __restrict__ etw_tab,
                                                 float* __restrict__ out) {
    __shared__ float s_as[512];
    __shared__ float s_sd[64], s_td[64];
    __shared__ float s_accR[512], s_accS[512], s_accT[512];
    __shared__ float s_gmax[8], s_den[8], s_wmax[64], s_etw[4];

    int n = blockIdx.x;
    int tid = threadIdx.x, warp = tid >> 5, lane = tid & 31;
    int start = g_off[n], cnt = g_cnt[n];

    for (int i = tid; i < 512; i += 256) {
        s_as[i] = g_attn[n * 512 + i] * g_rscale[i];
        s_accR[i] = 0.f; s_accS[i] = 0.f; s_accT[i] = 0.f;
    }
    if (tid < 64) {
        s_sd[tid] = __half2float(g_sn16[n * 64 + tid]);
        s_td[tid] = __half2float(g_tn16[n * 64 + tid]);
    }
    if (tid < 8) s_den[tid] = 0.f;
    if (tid < 4) s_etw[tid] = etw_tab[tid];
    __syncthreads();

    int h = lane >> 2, q = lane & 3;
    int kb = lane * 16, d0 = q * 16;
    float m = -1e30f, dsum = 0.f;
    float accR[16], accS[16], accT[16];
#pragma unroll
    for (int k = 0; k < 16; k++) { accR[k] = 0.f; accS[k] = 0.f; accT[k] = 0.f; }

    // prefetch pipeline state
    int i = warp;
    int packed = 0;
    int4 fA = make_int4(0, 0, 0, 0), fB = fA;
    float snm = 0.f, tnm = 0.f;
    if (i < cnt) {
        packed = g_ssrc[start + i];
        int s0i = packed & 0xFFFF;
        const int4* fp = (const int4*)(g_fs16 + (size_t)s0i * 512 + kb);
        fA = fp[0]; fB = fp[1];
        snm = g_snorm[s0i]; tnm = g_tnorm[s0i];
    }

    while (i < cnt) {
        int s = packed & 0xFFFF;
        float etw = s_etw[packed >> 16];

        // current s/t rows (issue loads early; consumed after the fs dot)
        const int4* sp = (const int4*)(g_sn16 + (size_t)s * 64 + d0);
        int4 s0 = sp[0], s1 = sp[1];
        const int4* tp = (const int4*)(g_tn16 + (size_t)s * 64 + d0);
        int4 t0 = tp[0], t1 = tp[1];

        // prefetch next edge
        int inext = i + 8;
        int pn = packed;
        int4 nA = fA, nB = fB;
        float nsn = snm, ntn = tnm;
        if (inext < cnt) {
            pn = g_ssrc[start + inext];
            int sn_ = pn & 0xFFFF;
            const int4* fpn = (const int4*)(g_fs16 + (size_t)sn_ * 512 + kb);
            nA = fpn[0]; nB = fpn[1];
            nsn = g_snorm[sn_]; ntn = g_tnorm[sn_];
        }

        const half2* h2a = (const half2*)&fA;
        const half2* h2b = (const half2*)&fB;
        const half2* sh0 = (const half2*)&s0; const half2* sh1 = (const half2*)&s1;
        const half2* th0 = (const half2*)&t0; const half2* th1 = (const half2*)&t1;

        float a = 0.f, cs = 0.f, ct = 0.f;
#pragma unroll
        for (int j = 0; j < 4; j++) {
            float2 f0 = __half22float2(h2a[j]);
            float2 f1 = __half22float2(h2b[j]);
            a += f0.x * s_as[kb + 2 * j]     + f0.y * s_as[kb + 2 * j + 1];
            a += f1.x * s_as[kb + 8 + 2 * j] + f1.y * s_as[kb + 8 + 2 * j + 1];
            float2 v0 = __half22float2(sh0[j]);
            float2 v1 = __half22float2(sh1[j]);
            cs += v0.x * s_sd[d0 + 2 * j]     + v0.y * s_sd[d0 + 2 * j + 1];
            cs += v1.x * s_sd[d0 + 8 + 2 * j] + v1.y * s_sd[d0 + 8 + 2 * j + 1];
            float2 w0 = __half22float2(th0[j]);
            float2 w1 = __half22float2(th1[j]);
            ct += w0.x * s_td[d0 + 2 * j]     + w0.y * s_td[d0 + 2 * j + 1];
            ct += w1.x * s_td[d0 + 8 + 2 * j] + w1.y * s_td[d0 + 8 + 2 * j + 1];
        }
        a  += __shfl_xor_sync(0xffffffffu, a, 1);
        cs += __shfl_xor_sync(0xffffffffu, cs, 1);
        ct += __shfl_xor_sync(0xffffffffu, ct, 1);
        a  += __shfl_xor_sync(0xffffffffu, a, 2);
        cs += __shfl_xor_sync(0xffffffffu, cs, 2);
        ct += __shfl_xor_sync(0xffffffffu, ct, 2);

        float sim = (TAOV * cs + (1.f - TAOV) * ct + 1.f) * 0.5f;
        float ev = sim * a * etw;

        float mnew = fmaxf(m, ev);
        float ex = __expf(ev - mnew);
        if (ev > m) {
            float so = __expf(m - mnew);
            dsum *= so;
#pragma unroll
            for (int k = 0; k < 16; k++) { accR[k] *= so; accS[k] *= so; accT[k] *= so; }
            m = mnew;
        }
        dsum += ex;

        float exs = ex * snm, ext = ex * tnm;
#pragma unroll
        for (int j = 0; j < 4; j++) {
            float2 f0 = __half22float2(h2a[j]);
            accR[2 * j]     += ex * f0.x;
            accR[2 * j + 1] += ex * f0.y;
            float2 f1 = __half22float2(h2b[j]);
            accR[8 + 2 * j]     += ex * f1.x;
            accR[8 + 2 * j + 1] += ex * f1.y;
            float2 v0 = __half22float2(sh0[j]);
            accS[2 * j]     += exs * v0.x;
            accS[2 * j + 1] += exs * v0.y;
            float2 v1 = __half22float2(sh1[j]);
            accS[8 + 2 * j]     += exs * v1.x;
            accS[8 + 2 * j + 1] += exs * v1.y;
            float2 w0 = __half22float2(th0[j]);
            accT[2 * j]     += ext * w0.x;
            accT[2 * j + 1] += ext * w0.y;
            float2 w1 = __half22float2(th1[j]);
            accT[8 + 2 * j]     += ext * w1.x;
            accT[8 + 2 * j + 1] += ext * w1.y;
        }

        packed = pn; fA = nA; fB = nB; snm = nsn; tnm = ntn;
        i = inext;
    }

    if (q == 0) s_wmax[warp * 8 + h] = m;
    __syncthreads();
    if (tid < 8) {
        float mm = -1e30f;
#pragma unroll
        for (int w = 0; w < 8; w++) mm = fmaxf(mm, s_wmax[w * 8 + tid]);
        s_gmax[tid] = mm;
    }
    __syncthreads();
    float sc = __expf(m - s_gmax[h]);
    if (q == 0) atomicAdd(&s_den[h], dsum * sc);
#pragma unroll
    for (int k = 0; k < 16; k++) {
        atomicAdd(&s_accR[kb + k], accR[k] * sc);
        atomicAdd(&s_accS[kb + k], accS[k] * sc);
        atomicAdd(&s_accT[kb + k], accT[k] * sc);
    }
    __syncthreads();

    if (tid < 64) {
        int d = tid;
        float rsum = 0.f, ssum = 0.f, tsum = 0.f;
#pragma unroll
        for (int hh = 0; hh < 8; hh++) {
            float den = s_den[hh];
            float inv = (den > 0.f) ? (1.f / den) : 0.f;
            float r = s_accR[hh * 64 + d] * inv + g_res[n * 512 + hh * 64 + d];
            rsum += fmaxf(r, 0.f);
            ssum += s_accS[hh * 64 + d] * inv;
            tsum += s_accT[hh * 64 + d] * inv;
        }
        out[n * 64 + d]               = rsum * 0.125f;
        out[NN * 64 + n * 64 + d]     = sloc[n * 64 + d] + ssum * 0.125f;
        out[2 * NN * 64 + n * 64 + d] = topo[n * 64 + d] + tsum * 0.125f;
    }
}

// ------------------- launch (k_gemm kept in profile slot 4) -------------------
extern "C" void kernel_launch(void* const* d_in, const int* in_sizes, int n_in,
                              void* d_out, int out_size) {
    const float* feat  = (const float*)d_in[0];
    const float* sloc  = (const float*)d_in[1];
    const float* topo  = (const float*)d_in[2];
    const float* Wp    = (const float*)d_in[3];
    const float* Wr    = (const float*)d_in[4];
    const float* Wprob = (const float*)d_in[5];
    const float* etw   = (const float*)d_in[6];
    const int*   src   = (const int*)d_in[7];
    const int*   dst   = (const int*)d_in[8];
    const int*   ef    = (const int*)d_in[9];
    float* out = (float*)d_out;
    int E = in_sizes[7];
    if (E > EMAX) E = EMAX;

    k_zero<<<7, 256>>>();                                   // 1
    k_hist<<<(E + 255) / 256, 256>>>(dst, E);               // 2
    k_rownorm<<<(NN + 3) / 4, 128>>>(sloc, topo);           // 3
    k_gemm<<<dim3(16, 13), 256>>>(feat, Wp, Wr);            // 4  <- ncu target
    k_attn<<<128, 256>>>(Wprob);                            // 5
    k_scan<<<1, 512>>>();                                   // 6
    k_scatter<<<(E + 255) / 256, 256>>>(dst, src, ef, E);   // 7
    k_edge<<<NN, 256>>>(sloc, topo, etw, out);              // 8
}

// round 11
// speedup vs baseline: 1.0766x; 1.0705x over previous
#include <cuda_runtime.h>
#include <cuda_fp16.h>
#include <cstdint>

#define NN   1546
#define ND   1373
#define KF   1546
#define KP   1568          // padded K (halves), 16B-aligned rows
#define HEADS 8
#define EMAX 210000
#define EPSV 1e-12f
#define TAOV 0.4f

// ------------------- scratch (device globals; no allocs allowed) -------------------
__device__ __align__(16) __half g_f16 [NN * KP];        // feat fp16, padded
__device__ __align__(16) __half g_w16 [4 * 512 * KP];   // W transposed [mat*2+g][n][k] fp16
__device__ __align__(16) __half g_fs16[NN * 512];       // feat_src fp16
__device__ __align__(16) float  g_res [NN * 512];       // resval fp32
__device__ __align__(16) float  g_attn[NN * 512];
__device__ __align__(16) __half g_sn16[NN * 64];
__device__ __align__(16) __half g_tn16[NN * 64];
__device__ float g_snorm[NN];
__device__ float g_tnorm[NN];
__device__ float g_colsq [512];
__device__ float g_rscale[512];
__device__ int   g_cnt[NN];
__device__ int   g_off[NN];
__device__ int   g_cur[NN];
__device__ int   g_ssrc[EMAX];    // sorted: src | (efeat<<16)

// ------------------- helpers -------------------
__device__ __forceinline__ void mma_f16(float* c, const uint32_t* a, const uint32_t* b) {
    asm volatile(
        "mma.sync.aligned.m16n8k16.row.col.f32.f16.f16.f32 "
        "{%0,%1,%2,%3}, {%4,%5,%6,%7}, {%8,%9}, {%0,%1,%2,%3};\n"
        : "+f"(c[0]), "+f"(c[1]), "+f"(c[2]), "+f"(c[3])
        : "r"(a[0]), "r"(a[1]), "r"(a[2]), "r"(a[3]), "r"(b[0]), "r"(b[1]));
}
__device__ __forceinline__ void ldmx4(uint32_t& r0, uint32_t& r1, uint32_t& r2, uint32_t& r3,
                                      uint32_t addr) {
    asm volatile("ldmatrix.sync.aligned.m8n8.x4.shared.b16 {%0,%1,%2,%3}, [%4];"
                 : "=r"(r0), "=r"(r1), "=r"(r2), "=r"(r3) : "r"(addr));
}

// ------------------- zero scratch counters -------------------
__global__ void k_zero() {
    int i = blockIdx.x * 256 + threadIdx.x;
    if (i < NN)  g_cnt[i] = 0;
    if (i < 512) g_colsq[i] = 0.f;
}

// ------------------- one-time fp16 conversion: feat + transposed W -------------------
__global__ __launch_bounds__(256) void k_cvt(const float* __restrict__ feat,
                                             const float* __restrict__ Wp,
                                             const float* __restrict__ Wr) {
    int z = blockIdx.z;
    int tx = threadIdx.x, ty = threadIdx.y;
    if (z < 4) {
        // transpose W[z/2][z&1]: [k][n] fp32 -> [n][k] fp16 padded
        __shared__ float t[32][33];
        int m = z >> 1, g = z & 1;
        const float* src = (m ? Wr : Wp) + (size_t)g * KF * 512;
        int k0 = blockIdx.x * 32, n0 = blockIdx.y * 32;
#pragma unroll
        for (int i = 0; i < 32; i += 8) {
            int k = k0 + ty + i;
            t[ty + i][tx] = (k < KF) ? src[(size_t)k * 512 + n0 + tx] : 0.f;
        }
        __syncthreads();
#pragma unroll
        for (int i = 0; i < 32; i += 8) {
            int n = n0 + ty + i;
            g_w16[(size_t)(z * 512 + n) * KP + k0 + tx] = __float2half_rn(t[tx][ty + i]);
        }
    } else {
        // feat fp32 -> fp16 padded rows
        int tid = (blockIdx.y * 49 + blockIdx.x) * 256 + ty * 32 + tx;
        int total = NN * KP;
        for (int idx = tid; idx < total; idx += 49 * 16 * 256) {
            int r = idx / KP, c = idx - r * KP;
            g_f16[idx] = (c < KF) ? __float2half_rn(feat[(size_t)r * KF + c]) : __float2half_rn(0.f);
        }
    }
}

// ------------- fp16 GEMM: BM=128 BN=64 BK=32, 256 thr, 2 CTA/SM, fp16 staging -------------
#define APADH 40
#define BPADH 40

__device__ __forceinline__ void ldA4(int rowb, int rowEnd, int k0, int tid, int4* pa) {
#pragma unroll
    for (int j = 0; j < 2; j++) {
        int idx = tid + j * 256;
        int r = idx >> 2, c = idx & 3;
        int gr = rowb + r;
        int4 v = make_int4(0, 0, 0, 0);
        if (gr < rowEnd) v = *(const int4*)(g_f16 + (size_t)gr * KP + k0 + c * 8);
        pa[j] = v;
    }
}
__device__ __forceinline__ void ldB4(const __half* Wb, int k0, int tid, int4* pb) {
    int n = tid >> 2, c = tid & 3;
    pb[0] = *(const int4*)(Wb + (size_t)n * KP + k0 + c * 8);
}
__device__ __forceinline__ void stA4(__half* As, int tid, const int4* pa) {
#pragma unroll
    for (int j = 0; j < 2; j++) {
        int idx = tid + j * 256;
        int r = idx >> 2, c = idx & 3;
        *(int4*)(As + r * APADH + c * 8) = pa[j];
    }
}
__device__ __forceinline__ void stB4(__half* Bs, int tid, const int4* pb) {
    int n = tid >> 2, c = tid & 3;
    *(int4*)(Bs + n * BPADH + c * 8) = pb[0];
}

__global__ __launch_bounds__(256, 2) void k_gemm() {
    __shared__ __align__(16) __half As[2][128 * APADH];
    __shared__ __align__(16) __half Bs[2][64 * BPADH];
    int tid = threadIdx.x, lane = tid & 31, warp = tid >> 5;
    int by = blockIdx.y, bx = blockIdx.x;

    int g, rowb, rowEnd;
    if (by < 11) { g = 0; rowb = by * 128; rowEnd = ND; }
    else         { g = 1; rowb = ND + (by - 11) * 128; rowEnd = NN; }

    int cb0 = bx * 64;
    int colb;
    bool isFs;
    int m;
    if (cb0 < 512) { m = 0; colb = cb0;       isFs = true; }
    else           { m = 1; colb = cb0 - 512; isFs = false; }
    const __half* Wb = g_w16 + (size_t)((m * 2 + g) * 512 + colb) * KP;

    float c[2][4][4];
#pragma unroll
    for (int i = 0; i < 2; i++)
#pragma unroll
        for (int j = 0; j < 4; j++)
#pragma unroll
            for (int k = 0; k < 4; k++) c[i][j][k] = 0.f;

    int4 pa[2], pb[1];
    ldA4(rowb, rowEnd, 0, tid, pa);
    ldB4(Wb, 0, tid, pb);
    stA4(As[0], tid, pa);
    stB4(Bs[0], tid, pb);
    __syncthreads();

    int p = 0;
    int warpM = warp >> 1, warpN = warp & 1;
    int l8 = lane & 7, grp = lane >> 3;
    int aRowOff = warpM * 32 + ((grp & 1) << 3) + l8;
    int aKOff   = (grp >> 1) << 3;
    int bNOff   = warpN * 32 + ((grp >> 1) << 3) + l8;
    int bKOff   = (grp & 1) << 3;

    for (int k0 = 0; k0 < KF; k0 += 32) {
        int kn = k0 + 32;
        if (kn < KF) { ldA4(rowb, rowEnd, kn, tid, pa); ldB4(Wb, kn, tid, pb); }

        uint32_t a_base = (uint32_t)__cvta_generic_to_shared(&As[p][0]);
        uint32_t b_base = (uint32_t)__cvta_generic_to_shared(&Bs[p][0]);
#pragma unroll
        for (int kk = 0; kk < 32; kk += 16) {
            uint32_t af[2][4], bf[4][2];
#pragma unroll
            for (int mt = 0; mt < 2; mt++) {
                uint32_t addr = a_base + (uint32_t)(((aRowOff + mt * 16) * APADH + kk + aKOff) * 2);
                ldmx4(af[mt][0], af[mt][1], af[mt][2], af[mt][3], addr);
            }
#pragma unroll
            for (int pr = 0; pr < 2; pr++) {
                uint32_t addr = b_base + (uint32_t)(((bNOff + pr * 16) * BPADH + kk + bKOff) * 2);
                ldmx4(bf[2 * pr][0], bf[2 * pr][1], bf[2 * pr + 1][0], bf[2 * pr + 1][1], addr);
            }
#pragma unroll
            for (int mt = 0; mt < 2; mt++)
#pragma unroll
                for (int nt = 0; nt < 4; nt++)
                    mma_f16(c[mt][nt], af[mt], bf[nt]);
        }

        if (kn < KF) {
            stA4(As[p ^ 1], tid, pa);
            stB4(Bs[p ^ 1], tid, pb);
            __syncthreads();
            p ^= 1;
        }
    }

#pragma unroll
    for (int mt = 0; mt < 2; mt++) {
        int row0 = rowb + warpM * 32 + mt * 16 + (lane >> 2);
#pragma unroll
        for (int nt = 0; nt < 4; nt++) {
            int col = colb + warpN * 32 + nt * 8 + (lane & 3) * 2;
            if (isFs) {
                if (row0 < rowEnd)
                    *(half2*)(g_fs16 + (size_t)row0 * 512 + col) = __floats2half2_rn(c[mt][nt][0], c[mt][nt][1]);
                if (row0 + 8 < rowEnd)
                    *(half2*)(g_fs16 + (size_t)(row0 + 8) * 512 + col) = __floats2half2_rn(c[mt][nt][2], c[mt][nt][3]);
            } else {
                if (row0 < rowEnd)
                    *(float2*)(g_res + (size_t)row0 * 512 + col) = make_float2(c[mt][nt][0], c[mt][nt][1]);
                if (row0 + 8 < rowEnd)
                    *(float2*)(g_res + (size_t)(row0 + 8) * 512 + col) = make_float2(c[mt][nt][2], c[mt][nt][3]);
            }
        }
    }
}

// ------------------- ft_attn + column sq-sums (fused), reads fs16 -------------------
#define ATTN_CH 97
__global__ __launch_bounds__(256) void k_attn(const float* __restrict__ Wprob) {
    __shared__ float Wh[4096];
    __shared__ float fsh[8][64];
    __shared__ float s_csq[64];
    int tid = threadIdx.x, warp = tid >> 5, lane = tid & 31;
    int h = blockIdx.x & 7, chunk = blockIdx.x >> 3;
    const float* W = Wprob + h * 4096;
    for (int i = tid; i < 4096; i += 256) Wh[i] = W[i];
    if (tid < 64) s_csq[tid] = 0.f;
    __syncthreads();

    float sq0 = 0.f, sq1 = 0.f;
    int n0 = chunk * ATTN_CH;
    int n1 = min(n0 + ATTN_CH, NN);
    for (int n = n0 + warp; n < n1; n += 8) {
        float v0 = __half2float(g_fs16[n * 512 + h * 64 + lane]);
        float v1 = __half2float(g_fs16[n * 512 + h * 64 + lane + 32]);
        fsh[warp][lane]      = v0;
        fsh[warp][lane + 32] = v1;
        sq0 += v0 * v0;
        sq1 += v1 * v1;
        __syncwarp();
        float a0 = 0.f, a1 = 0.f;
#pragma unroll 8
        for (int d = 0; d < 64; d++) {
            float f = fsh[warp][d];
            a0 += f * Wh[d * 64 + lane];
            a1 += f * Wh[d * 64 + lane + 32];
        }
        float t0 = tanhf(a0), t1 = tanhf(a1);
        float m = fmaxf(t0, t1);
#pragma unroll
        for (int off = 16; off; off >>= 1) m = fmaxf(m, __shfl_xor_sync(0xffffffffu, m, off));
        float e0 = __expf(t0 - m), e1 = __expf(t1 - m);
        float s = e0 + e1;
#pragma unroll
        for (int off = 16; off; off >>= 1) s += __shfl_xor_sync(0xffffffffu, s, off);
        float inv = 1.f / s;
        g_attn[n * 512 + h * 64 + lane]      = e0 * inv;
        g_attn[n * 512 + h * 64 + lane + 32] = e1 * inv;
        __syncwarp();
    }
    atomicAdd(&s_csq[lane], sq0);
    atomicAdd(&s_csq[lane + 32], sq1);
    __syncthreads();
    if (tid < 64) atomicAdd(&g_colsq[h * 64 + tid], s_csq[tid]);
}

// ------------------- row norms of sloc / topo -------------------
__global__ __launch_bounds__(128) void k_rownorm(const float* __restrict__ sloc,
                                                 const float* __restrict__ topo) {
    int warp = threadIdx.x >> 5, lane = threadIdx.x & 31;
    int n = blockIdx.x * 4 + warp;
    if (n >= NN) return;
    float2 sv = *(const float2*)(sloc + (size_t)n * 64 + 2 * lane);
    float2 tv = *(const float2*)(topo + (size_t)n * 64 + 2 * lane);
    float ss = sv.x * sv.x + sv.y * sv.y;
    float tt = tv.x * tv.x + tv.y * tv.y;
#pragma unroll
    for (int off = 16; off; off >>= 1) {
        ss += __shfl_xor_sync(0xffffffffu, ss, off);
        tt += __shfl_xor_sync(0xffffffffu, tt, off);
    }
    float sn = fmaxf(sqrtf(ss), EPSV), tn = fmaxf(sqrtf(tt), EPSV);
    float si = 1.f / sn, ti = 1.f / tn;
    ((half2*)(g_sn16 + (size_t)n * 64))[lane] = __floats2half2_rn(sv.x * si, sv.y * si);
    ((half2*)(g_tn16 + (size_t)n * 64))[lane] = __floats2half2_rn(tv.x * ti, tv.y * ti);
    if (lane == 0) { g_snorm[n] = sn; g_tnorm[n] = tn; }
}

// ------------------- counting sort of edges by dst -------------------
__global__ void k_hist(const int* __restrict__ dst, int E) {
    int e = blockIdx.x * 256 + threadIdx.x;
    if (e < E) atomicAdd(&g_cnt[dst[e]], 1);
}
__global__ __launch_bounds__(512) void k_scan() {
    __shared__ int sh[512];
    int t = threadIdx.x;
    int base = t * 4;
    int v0 = (base     < NN) ? g_cnt[base]     : 0;
    int v1 = (base + 1 < NN) ? g_cnt[base + 1] : 0;
    int v2 = (base + 2 < NN) ? g_cnt[base + 2] : 0;
    int v3 = (base + 3 < NN) ? g_cnt[base + 3] : 0;
    int p0 = v0, p1 = p0 + v1, p2 = p1 + v2, p3 = p2 + v3;
    sh[t] = p3;
    __syncthreads();
    for (int off = 1; off < 512; off <<= 1) {
        int x = 0;
        if (t >= off) x = sh[t - off];
        __syncthreads();
        sh[t] += x;
        __syncthreads();
    }
    int excl = sh[t] - p3;
    if (base     < NN) { g_off[base]     = excl;      g_cur[base]     = excl; }
    if (base + 1 < NN) { g_off[base + 1] = excl + p0; g_cur[base + 1] = excl + p0; }
    if (base + 2 < NN) { g_off[base + 2] = excl + p1; g_cur[base + 2] = excl + p1; }
    if (base + 3 < NN) { g_off[base + 3] = excl + p2; g_cur[base + 3] = excl + p2; }
    g_rscale[t] = 1.f / fmaxf(sqrtf(g_colsq[t]), EPSV);
}
__global__ void k_scatter(const int* __restrict__ dst, const int* __restrict__ src,
                          const int* __restrict__ efeat, int E) {
    int e = blockIdx.x * 256 + threadIdx.x;
    if (e < E) {
        int pos = atomicAdd(&g_cur[dst[e]], 1);
        g_ssrc[pos] = src[e] | (efeat[e] << 16);
    }
}

// ------------------- edge phase: online softmax, prefetched gathers -------------------
__global__ __launch_bounds__(256, 2) void k_edge(const float* __restrict__ sloc,
                                                 const float* __restrict__ topo,
                                                 const float* __restrict__ etw_tab,
                                                 float* __restrict__ out) {
    __shared__ float s_as[512];
    __shared__ float s_sd[64], s_td[64];
    __shared__ float s_accR[512], s_accS[512], s_accT[512];
    __shared__ float s_gmax[8], s_den[8], s_wmax[64], s_etw[4];

    int n = blockIdx.x;
    int tid = threadIdx.x, warp = tid >> 5, lane = tid & 31;
    int start = g_off[n], cnt = g_cnt[n];

    for (int i = tid; i < 512; i += 256) {
        s_as[i] = g_attn[n * 512 + i] * g_rscale[i];
        s_accR[i] = 0.f; s_accS[i] = 0.f; s_accT[i] = 0.f;
    }
    if (tid < 64) {
        s_sd[tid] = __half2float(g_sn16[n * 64 + tid]);
        s_td[tid] = __half2float(g_tn16[n * 64 + tid]);
    }
    if (tid < 8) s_den[tid] = 0.f;
    if (tid < 4) s_etw[tid] = etw_tab[tid];
    __syncthreads();

    int h = lane >> 2, q = lane & 3;
    int kb = lane * 16, d0 = q * 16;
    float m = -1e30f, dsum = 0.f;
    float accR[16], accS[16], accT[16];
#pragma unroll
    for (int k = 0; k < 16; k++) { accR[k] = 0.f; accS[k] = 0.f; accT[k] = 0.f; }

    int i = warp;
    int packed = 0;
    int4 fA = make_int4(0, 0, 0, 0), fB = fA;
    float snm = 0.f, tnm = 0.f;
    if (i < cnt) {
        packed = g_ssrc[start + i];
        int s0i = packed & 0xFFFF;
        const int4* fp = (const int4*)(g_fs16 + (size_t)s0i * 512 + kb);
        fA = fp[0]; fB = fp[1];
        snm = g_snorm[s0i]; tnm = g_tnorm[s0i];
    }

    while (i < cnt) {
        int s = packed & 0xFFFF;
        float etw = s_etw[packed >> 16];

        const int4* sp = (const int4*)(g_sn16 + (size_t)s * 64 + d0);
        int4 s0 = sp[0], s1 = sp[1];
        const int4* tp = (const int4*)(g_tn16 + (size_t)s * 64 + d0);
        int4 t0 = tp[0], t1 = tp[1];

        int inext = i + 8;
        int pn = packed;
        int4 nA = fA, nB = fB;
        float nsn = snm, ntn = tnm;
        if (inext < cnt) {
            pn = g_ssrc[start + inext];
            int sn_ = pn & 0xFFFF;
            const int4* fpn = (const int4*)(g_fs16 + (size_t)sn_ * 512 + kb);
            nA = fpn[0]; nB = fpn[1];
            nsn = g_snorm[sn_]; ntn = g_tnorm[sn_];
        }

        const half2* h2a = (const half2*)&fA;
        const half2* h2b = (const half2*)&fB;
        const half2* sh0 = (const half2*)&s0; const half2* sh1 = (const half2*)&s1;
        const half2* th0 = (const half2*)&t0; const half2* th1 = (const half2*)&t1;

        float a = 0.f, cs = 0.f, ct = 0.f;
#pragma unroll
        for (int j = 0; j < 4; j++) {
            float2 f0 = __half22float2(h2a[j]);
            float2 f1 = __half22float2(h2b[j]);
            a += f0.x * s_as[kb + 2 * j]     + f0.y * s_as[kb + 2 * j + 1];
            a += f1.x * s_as[kb + 8 + 2 * j] + f1.y * s_as[kb + 8 + 2 * j + 1];
            float2 v0 = __half22float2(sh0[j]);
            float2 v1 = __half22float2(sh1[j]);
            cs += v0.x * s_sd[d0 + 2 * j]     + v0.y * s_sd[d0 + 2 * j + 1];
            cs += v1.x * s_sd[d0 + 8 + 2 * j] + v1.y * s_sd[d0 + 8 + 2 * j + 1];
            float2 w0 = __half22float2(th0[j]);
            float2 w1 = __half22float2(th1[j]);
            ct += w0.x * s_td[d0 + 2 * j]     + w0.y * s_td[d0 + 2 * j + 1];
            ct += w1.x * s_td[d0 + 8 + 2 * j] + w1.y * s_td[d0 + 8 + 2 * j + 1];
        }
        a  += __shfl_xor_sync(0xffffffffu, a, 1);
        cs += __shfl_xor_sync(0xffffffffu, cs, 1);
        ct += __shfl_xor_sync(0xffffffffu, ct, 1);
        a  += __shfl_xor_sync(0xffffffffu, a, 2);
        cs += __shfl_xor_sync(0xffffffffu, cs, 2);
        ct += __shfl_xor_sync(0xffffffffu, ct, 2);

        float sim = (TAOV * cs + (1.f - TAOV) * ct + 1.f) * 0.5f;
        float ev = sim * a * etw;

        float mnew = fmaxf(m, ev);
        float ex = __expf(ev - mnew);
        if (ev > m) {
            float so = __expf(m - mnew);
            dsum *= so;
#pragma unroll
            for (int k = 0; k < 16; k++) { accR[k] *= so; accS[k] *= so; accT[k] *= so; }
            m = mnew;
        }
        dsum += ex;

        float exs = ex * snm, ext = ex * tnm;
#pragma unroll
        for (int j = 0; j < 4; j++) {
            float2 f0 = __half22float2(h2a[j]);
            accR[2 * j]     += ex * f0.x;
            accR[2 * j + 1] += ex * f0.y;
            float2 f1 = __half22float2(h2b[j]);
            accR[8 + 2 * j]     += ex * f1.x;
            accR[8 + 2 * j + 1] += ex * f1.y;
            float2 v0 = __half22float2(sh0[j]);
            accS[2 * j]     += exs * v0.x;
            accS[2 * j + 1] += exs * v0.y;
            float2 v1 = __half22float2(sh1[j]);
            accS[8 + 2 * j]     += exs * v1.x;
            accS[8 + 2 * j + 1] += exs * v1.y;
            float2 w0 = __half22float2(th0[j]);
            accT[2 * j]     += ext * w0.x;
            accT[2 * j + 1] += ext * w0.y;
            float2 w1 = __half22float2(th1[j]);
            accT[8 + 2 * j]     += ext * w1.x;
            accT[8 + 2 * j + 1] += ext * w1.y;
        }

        packed = pn; fA = nA; fB = nB; snm = nsn; tnm = ntn;
        i = inext;
    }

    if (q == 0) s_wmax[warp * 8 + h] = m;
    __syncthreads();
    if (tid < 8) {
        float mm = -1e30f;
#pragma unroll
        for (int w = 0; w < 8; w++) mm = fmaxf(mm, s_wmax[w * 8 + tid]);
        s_gmax[tid] = mm;
    }
    __syncthreads();
    float sc = __expf(m - s_gmax[h]);
    if (q == 0) atomicAdd(&s_den[h], dsum * sc);
#pragma unroll
    for (int k = 0; k < 16; k++) {
        atomicAdd(&s_accR[kb + k], accR[k] * sc);
        atomicAdd(&s_accS[kb + k], accS[k] * sc);
        atomicAdd(&s_accT[kb + k], accT[k] * sc);
    }
    __syncthreads();

    if (tid < 64) {
        int d = tid;
        float rsum = 0.f, ssum = 0.f, tsum = 0.f;
#pragma unroll
        for (int hh = 0; hh < 8; hh++) {
            float den = s_den[hh];
            float inv = (den > 0.f) ? (1.f / den) : 0.f;
            float r = s_accR[hh * 64 + d] * inv + g_res[n * 512 + hh * 64 + d];
            rsum += fmaxf(r, 0.f);
            ssum += s_accS[hh * 64 + d] * inv;
            tsum += s_accT[hh * 64 + d] * inv;
        }
        out[n * 64 + d]               = rsum * 0.125f;
        out[NN * 64 + n * 64 + d]     = sloc[n * 64 + d] + ssum * 0.125f;
        out[2 * NN * 64 + n * 64 + d] = topo[n * 64 + d] + tsum * 0.125f;
    }
}

// ------------------- launch (k_gemm kept in profile slot 4) -------------------
extern "C" void kernel_launch(void* const* d_in, const int* in_sizes, int n_in,
                              void* d_out, int out_size) {
    const float* feat  = (const float*)d_in[0];
    const float* sloc  = (const float*)d_in[1];
    const float* topo  = (const float*)d_in[2];
    const float* Wp    = (const float*)d_in[3];
    const float* Wr    = (const float*)d_in[4];
    const float* Wprob = (const float*)d_in[5];
    const float* etw   = (const float*)d_in[6];
    const int*   src   = (const int*)d_in[7];
    const int*   dst   = (const int*)d_in[8];
    const int*   ef    = (const int*)d_in[9];
    float* out = (float*)d_out;
    int E = in_sizes[7];
    if (E > EMAX) E = EMAX;

    k_zero<<<7, 256>>>();                                   // 1
    k_cvt<<<dim3(49, 16, 5), dim3(32, 8)>>>(feat, Wp, Wr);  // 2
    k_hist<<<(E + 255) / 256, 256>>>(dst, E);               // 3
    k_gemm<<<dim3(16, 13), 256>>>();                        // 4  <- ncu target
    k_rownorm<<<(NN + 3) / 4, 128>>>(sloc, topo);           // 5
    k_attn<<<128, 256>>>(Wprob);                            // 6
    k_scan<<<1, 512>>>();                                   // 7
    k_scatter<<<(E + 255) / 256, 256>>>(dst, src, ef, E);   // 8
    k_edge<<<NN, 256>>>(sloc, topo, etw, out);              // 9
}

// round 12
// speedup vs baseline: 1.1558x; 1.0736x over previous
#include <cuda_runtime.h>
#include <cuda_fp16.h>
#include <cstdint>

#define NN   1546
#define ND   1373
#define KF   1546
#define KP   1568          // padded K (halves), 16B-aligned rows
#define HEADS 8
#define EMAX 210000
#define EPSV 1e-12f
#define TAOV 0.4f

// ------------------- scratch (device globals; no allocs allowed) -------------------
__device__ __align__(16) __half g_f16 [NN * KP];        // feat fp16, padded
__device__ __align__(16) __half g_w16 [4 * 512 * KP];   // W transposed [mat*2+g][n][k] fp16
__device__ __align__(16) __half g_fs16[NN * 512];       // feat_src fp16
__device__ __align__(16) float  g_res [NN * 512];       // resval fp32
__device__ __align__(16) float  g_attn[NN * 512];
__device__ __align__(16) __half g_sn16[NN * 64];
__device__ __align__(16) __half g_tn16[NN * 64];
__device__ float g_snorm[NN];
__device__ float g_tnorm[NN];
__device__ float g_colsq [512];
__device__ float g_rscale[512];
__device__ int   g_cnt[NN];
__device__ int   g_off[NN];
__device__ int   g_cur[NN];
__device__ int   g_ssrc[EMAX];    // sorted: src | (efeat<<16)

// ------------------- helpers -------------------
__device__ __forceinline__ void mma_f16(float* c, const uint32_t* a, const uint32_t* b) {
    asm volatile(
        "mma.sync.aligned.m16n8k16.row.col.f32.f16.f16.f32 "
        "{%0,%1,%2,%3}, {%4,%5,%6,%7}, {%8,%9}, {%0,%1,%2,%3};\n"
        : "+f"(c[0]), "+f"(c[1]), "+f"(c[2]), "+f"(c[3])
        : "r"(a[0]), "r"(a[1]), "r"(a[2]), "r"(a[3]), "r"(b[0]), "r"(b[1]));
}
__device__ __forceinline__ void ldmx4(uint32_t& r0, uint32_t& r1, uint32_t& r2, uint32_t& r3,
                                      uint32_t addr) {
    asm volatile("ldmatrix.sync.aligned.m8n8.x4.shared.b16 {%0,%1,%2,%3}, [%4];"
                 : "=r"(r0), "=r"(r1), "=r"(r2), "=r"(r3) : "r"(addr));
}

// ------------------- zero scratch counters -------------------
__global__ void k_zero() {
    int i = blockIdx.x * 256 + threadIdx.x;
    if (i < NN)  g_cnt[i] = 0;
    if (i < 512) g_colsq[i] = 0.f;
}

// ------------------- one-time fp16 conversion: feat + transposed W -------------------
__global__ __launch_bounds__(256) void k_cvt(const float* __restrict__ feat,
                                             const float* __restrict__ Wp,
                                             const float* __restrict__ Wr) {
    int z = blockIdx.z;
    int tx = threadIdx.x, ty = threadIdx.y;
    if (z < 4) {
        __shared__ float t[32][33];
        int m = z >> 1, g = z & 1;
        const float* src = (m ? Wr : Wp) + (size_t)g * KF * 512;
        int k0 = blockIdx.x * 32, n0 = blockIdx.y * 32;
#pragma unroll
        for (int i = 0; i < 32; i += 8) {
            int k = k0 + ty + i;
            t[ty + i][tx] = (k < KF) ? src[(size_t)k * 512 + n0 + tx] : 0.f;
        }
        __syncthreads();
#pragma unroll
        for (int i = 0; i < 32; i += 8) {
            int n = n0 + ty + i;
            g_w16[(size_t)(z * 512 + n) * KP + k0 + tx] = __float2half_rn(t[tx][ty + i]);
        }
    } else {
        int tid = (blockIdx.y * 49 + blockIdx.x) * 256 + ty * 32 + tx;
        int total = NN * KP;
        for (int idx = tid; idx < total; idx += 49 * 16 * 256) {
            int r = idx / KP, c = idx - r * KP;
            g_f16[idx] = (c < KF) ? __float2half_rn(feat[(size_t)r * KF + c]) : __float2half_rn(0.f);
        }
    }
}

// ------------- fp16 GEMM: BM=128 BN=64 BK=32, 256 thr, 2 CTA/SM, fp16 staging -------------
#define APADH 40
#define BPADH 40

__device__ __forceinline__ void ldA4(int rowb, int rowEnd, int k0, int tid, int4* pa) {
#pragma unroll
    for (int j = 0; j < 2; j++) {
        int idx = tid + j * 256;
        int r = idx >> 2, c = idx & 3;
        int gr = rowb + r;
        int4 v = make_int4(0, 0, 0, 0);
        if (gr < rowEnd) v = *(const int4*)(g_f16 + (size_t)gr * KP + k0 + c * 8);
        pa[j] = v;
    }
}
__device__ __forceinline__ void ldB4(const __half* Wb, int k0, int tid, int4* pb) {
    int n = tid >> 2, c = tid & 3;
    pb[0] = *(const int4*)(Wb + (size_t)n * KP + k0 + c * 8);
}
__device__ __forceinline__ void stA4(__half* As, int tid, const int4* pa) {
#pragma unroll
    for (int j = 0; j < 2; j++) {
        int idx = tid + j * 256;
        int r = idx >> 2, c = idx & 3;
        *(int4*)(As + r * APADH + c * 8) = pa[j];
    }
}
__device__ __forceinline__ void stB4(__half* Bs, int tid, const int4* pb) {
    int n = tid >> 2, c = tid & 3;
    *(int4*)(Bs + n * BPADH + c * 8) = pb[0];
}

__global__ __launch_bounds__(256, 2) void k_gemm() {
    __shared__ __align__(16) __half As[2][128 * APADH];
    __shared__ __align__(16) __half Bs[2][64 * BPADH];
    int tid = threadIdx.x, lane = tid & 31, warp = tid >> 5;
    int by = blockIdx.y, bx = blockIdx.x;

    int g, rowb, rowEnd;
    if (by < 11) { g = 0; rowb = by * 128; rowEnd = ND; }
    else         { g = 1; rowb = ND + (by - 11) * 128; rowEnd = NN; }

    int cb0 = bx * 64;
    int colb;
    bool isFs;
    int m;
    if (cb0 < 512) { m = 0; colb = cb0;       isFs = true; }
    else           { m = 1; colb = cb0 - 512; isFs = false; }
    const __half* Wb = g_w16 + (size_t)((m * 2 + g) * 512 + colb) * KP;

    float c[2][4][4];
#pragma unroll
    for (int i = 0; i < 2; i++)
#pragma unroll
        for (int j = 0; j < 4; j++)
#pragma unroll
            for (int k = 0; k < 4; k++) c[i][j][k] = 0.f;

    int4 pa[2], pb[1];
    ldA4(rowb, rowEnd, 0, tid, pa);
    ldB4(Wb, 0, tid, pb);
    stA4(As[0], tid, pa);
    stB4(Bs[0], tid, pb);
    __syncthreads();

    int p = 0;
    int warpM = warp >> 1, warpN = warp & 1;
    int l8 = lane & 7, grp = lane >> 3;
    int aRowOff = warpM * 32 + ((grp & 1) << 3) + l8;
    int aKOff   = (grp >> 1) << 3;
    int bNOff   = warpN * 32 + ((grp >> 1) << 3) + l8;
    int bKOff   = (grp & 1) << 3;

    for (int k0 = 0; k0 < KF; k0 += 32) {
        int kn = k0 + 32;
        if (kn < KF) { ldA4(rowb, rowEnd, kn, tid, pa); ldB4(Wb, kn, tid, pb); }

        uint32_t a_base = (uint32_t)__cvta_generic_to_shared(&As[p][0]);
        uint32_t b_base = (uint32_t)__cvta_generic_to_shared(&Bs[p][0]);
#pragma unroll
        for (int kk = 0; kk < 32; kk += 16) {
            uint32_t af[2][4], bf[4][2];
#pragma unroll
            for (int mt = 0; mt < 2; mt++) {
                uint32_t addr = a_base + (uint32_t)(((aRowOff + mt * 16) * APADH + kk + aKOff) * 2);
                ldmx4(af[mt][0], af[mt][1], af[mt][2], af[mt][3], addr);
            }
#pragma unroll
            for (int pr = 0; pr < 2; pr++) {
                uint32_t addr = b_base + (uint32_t)(((bNOff + pr * 16) * BPADH + kk + bKOff) * 2);
                ldmx4(bf[2 * pr][0], bf[2 * pr][1], bf[2 * pr + 1][0], bf[2 * pr + 1][1], addr);
            }
#pragma unroll
            for (int mt = 0; mt < 2; mt++)
#pragma unroll
                for (int nt = 0; nt < 4; nt++)
                    mma_f16(c[mt][nt], af[mt], bf[nt]);
        }

        if (kn < KF) {
            stA4(As[p ^ 1], tid, pa);
            stB4(Bs[p ^ 1], tid, pb);
            __syncthreads();
            p ^= 1;
        }
    }

#pragma unroll
    for (int mt = 0; mt < 2; mt++) {
        int row0 = rowb + warpM * 32 + mt * 16 + (lane >> 2);
#pragma unroll
        for (int nt = 0; nt < 4; nt++) {
            int col = colb + warpN * 32 + nt * 8 + (lane & 3) * 2;
            if (isFs) {
                if (row0 < rowEnd)
                    *(half2*)(g_fs16 + (size_t)row0 * 512 + col) = __floats2half2_rn(c[mt][nt][0], c[mt][nt][1]);
                if (row0 + 8 < rowEnd)
                    *(half2*)(g_fs16 + (size_t)(row0 + 8) * 512 + col) = __floats2half2_rn(c[mt][nt][2], c[mt][nt][3]);
            } else {
                if (row0 < rowEnd)
                    *(float2*)(g_res + (size_t)row0 * 512 + col) = make_float2(c[mt][nt][0], c[mt][nt][1]);
                if (row0 + 8 < rowEnd)
                    *(float2*)(g_res + (size_t)(row0 + 8) * 512 + col) = make_float2(c[mt][nt][2], c[mt][nt][3]);
            }
        }
    }
}

// ------------------- ft_attn + column sq-sums (fused), reads fs16 -------------------
#define ATTN_CH 97
__global__ __launch_bounds__(256) void k_attn(const float* __restrict__ Wprob) {
    __shared__ float Wh[4096];
    __shared__ float fsh[8][64];
    __shared__ float s_csq[64];
    int tid = threadIdx.x, warp = tid >> 5, lane = tid & 31;
    int h = blockIdx.x & 7, chunk = blockIdx.x >> 3;
    const float* W = Wprob + h * 4096;
    for (int i = tid; i < 4096; i += 256) Wh[i] = W[i];
    if (tid < 64) s_csq[tid] = 0.f;
    __syncthreads();

    float sq0 = 0.f, sq1 = 0.f;
    int n0 = chunk * ATTN_CH;
    int n1 = min(n0 + ATTN_CH, NN);
    for (int n = n0 + warp; n < n1; n += 8) {
        float v0 = __half2float(g_fs16[n * 512 + h * 64 + lane]);
        float v1 = __half2float(g_fs16[n * 512 + h * 64 + lane + 32]);
        fsh[warp][lane]      = v0;
        fsh[warp][lane + 32] = v1;
        sq0 += v0 * v0;
        sq1 += v1 * v1;
        __syncwarp();
        float a0 = 0.f, a1 = 0.f;
#pragma unroll 8
        for (int d = 0; d < 64; d++) {
            float f = fsh[warp][d];
            a0 += f * Wh[d * 64 + lane];
            a1 += f * Wh[d * 64 + lane + 32];
        }
        float t0 = tanhf(a0), t1 = tanhf(a1);
        float m = fmaxf(t0, t1);
#pragma unroll
        for (int off = 16; off; off >>= 1) m = fmaxf(m, __shfl_xor_sync(0xffffffffu, m, off));
        float e0 = __expf(t0 - m), e1 = __expf(t1 - m);
        float s = e0 + e1;
#pragma unroll
        for (int off = 16; off; off >>= 1) s += __shfl_xor_sync(0xffffffffu, s, off);
        float inv = 1.f / s;
        g_attn[n * 512 + h * 64 + lane]      = e0 * inv;
        g_attn[n * 512 + h * 64 + lane + 32] = e1 * inv;
        __syncwarp();
    }
    atomicAdd(&s_csq[lane], sq0);
    atomicAdd(&s_csq[lane + 32], sq1);
    __syncthreads();
    if (tid < 64) atomicAdd(&g_colsq[h * 64 + tid], s_csq[tid]);
}

// ------------------- row norms of sloc / topo -------------------
__global__ __launch_bounds__(128) void k_rownorm(const float* __restrict__ sloc,
                                                 const float* __restrict__ topo) {
    int warp = threadIdx.x >> 5, lane = threadIdx.x & 31;
    int n = blockIdx.x * 4 + warp;
    if (n >= NN) return;
    float2 sv = *(const float2*)(sloc + (size_t)n * 64 + 2 * lane);
    float2 tv = *(const float2*)(topo + (size_t)n * 64 + 2 * lane);
    float ss = sv.x * sv.x + sv.y * sv.y;
    float tt = tv.x * tv.x + tv.y * tv.y;
#pragma unroll
    for (int off = 16; off; off >>= 1) {
        ss += __shfl_xor_sync(0xffffffffu, ss, off);
        tt += __shfl_xor_sync(0xffffffffu, tt, off);
    }
    float sn = fmaxf(sqrtf(ss), EPSV), tn = fmaxf(sqrtf(tt), EPSV);
    float si = 1.f / sn, ti = 1.f / tn;
    ((half2*)(g_sn16 + (size_t)n * 64))[lane] = __floats2half2_rn(sv.x * si, sv.y * si);
    ((half2*)(g_tn16 + (size_t)n * 64))[lane] = __floats2half2_rn(tv.x * ti, tv.y * ti);
    if (lane == 0) { g_snorm[n] = sn; g_tnorm[n] = tn; }
}

// ------------------- counting sort of edges by dst -------------------
__global__ void k_hist(const int* __restrict__ dst, int E) {
    int e = blockIdx.x * 256 + threadIdx.x;
    if (e < E) atomicAdd(&g_cnt[dst[e]], 1);
}
__global__ __launch_bounds__(512) void k_scan() {
    __shared__ int sh[512];
    int t = threadIdx.x;
    int base = t * 4;
    int v0 = (base     < NN) ? g_cnt[base]     : 0;
    int v1 = (base + 1 < NN) ? g_cnt[base + 1] : 0;
    int v2 = (base + 2 < NN) ? g_cnt[base + 2] : 0;
    int v3 = (base + 3 < NN) ? g_cnt[base + 3] : 0;
    int p0 = v0, p1 = p0 + v1, p2 = p1 + v2, p3 = p2 + v3;
    sh[t] = p3;
    __syncthreads();
    for (int off = 1; off < 512; off <<= 1) {
        int x = 0;
        if (t >= off) x = sh[t - off];
        __syncthreads();
        sh[t] += x;
        __syncthreads();
    }
    int excl = sh[t] - p3;
    if (base     < NN) { g_off[base]     = excl;      g_cur[base]     = excl; }
    if (base + 1 < NN) { g_off[base + 1] = excl + p0; g_cur[base + 1] = excl + p0; }
    if (base + 2 < NN) { g_off[base + 2] = excl + p1; g_cur[base + 2] = excl + p1; }
    if (base + 3 < NN) { g_off[base + 3] = excl + p2; g_cur[base + 3] = excl + p2; }
    g_rscale[t] = 1.f / fmaxf(sqrtf(g_colsq[t]), EPSV);
}
__global__ void k_scatter(const int* __restrict__ dst, const int* __restrict__ src,
                          const int* __restrict__ efeat, int E) {
    int e = blockIdx.x * 256 + threadIdx.x;
    if (e < E) {
        int pos = atomicAdd(&g_cur[dst[e]], 1);
        g_ssrc[pos] = src[e] | (efeat[e] << 16);
    }
}

// ----- edge phase: shift-free softmax (|ev| < 1 provably), independent iterations -----
__global__ __launch_bounds__(256, 2) void k_edge(const float* __restrict__ sloc,
                                                 const float* __restrict__ topo,
                                                 const float* __restrict__ etw_tab,
                                                 float* __restrict__ out) {
    __shared__ float s_as[512];
    __shared__ float s_sd[64], s_td[64];
    __shared__ float s_accR[512], s_accS[512], s_accT[512];
    __shared__ float s_den[8], s_etw[4];

    int n = blockIdx.x;
    int tid = threadIdx.x, warp = tid >> 5, lane = tid & 31;
    int start = g_off[n], cnt = g_cnt[n];

    for (int i = tid; i < 512; i += 256) {
        s_as[i] = g_attn[n * 512 + i] * g_rscale[i];
        s_accR[i] = 0.f; s_accS[i] = 0.f; s_accT[i] = 0.f;
    }
    if (tid < 64) {
        s_sd[tid] = __half2float(g_sn16[n * 64 + tid]);
        s_td[tid] = __half2float(g_tn16[n * 64 + tid]);
    }
    if (tid < 8) s_den[tid] = 0.f;
    if (tid < 4) s_etw[tid] = etw_tab[tid];
    __syncthreads();

    int h = lane >> 2, q = lane & 3;
    int kb = lane * 16, d0 = q * 16;
    float dsum = 0.f;
    float accR[16], accS[16], accT[16];
#pragma unroll
    for (int k = 0; k < 16; k++) { accR[k] = 0.f; accS[k] = 0.f; accT[k] = 0.f; }

    // prefetch pipeline state
    int i = warp;
    int packed = 0;
    int4 fA = make_int4(0, 0, 0, 0), fB = fA;
    float snm = 0.f, tnm = 0.f;
    if (i < cnt) {
        packed = g_ssrc[start + i];
        int s0i = packed & 0xFFFF;
        const int4* fp = (const int4*)(g_fs16 + (size_t)s0i * 512 + kb);
        fA = fp[0]; fB = fp[1];
        snm = g_snorm[s0i]; tnm = g_tnorm[s0i];
    }

    while (i < cnt) {
        int s = packed & 0xFFFF;
        float etw = s_etw[packed >> 16];

        const int4* sp = (const int4*)(g_sn16 + (size_t)s * 64 + d0);
        int4 s0 = sp[0], s1 = sp[1];
        const int4* tp = (const int4*)(g_tn16 + (size_t)s * 64 + d0);
        int4 t0 = tp[0], t1 = tp[1];

        int inext = i + 8;
        int pn = packed;
        int4 nA = fA, nB = fB;
        float nsn = snm, ntn = tnm;
        if (inext < cnt) {
            pn = g_ssrc[start + inext];
            int sn_ = pn & 0xFFFF;
            const int4* fpn = (const int4*)(g_fs16 + (size_t)sn_ * 512 + kb);
            nA = fpn[0]; nB = fpn[1];
            nsn = g_snorm[sn_]; ntn = g_tnorm[sn_];
        }

        const half2* h2a = (const half2*)&fA;
        const half2* h2b = (const half2*)&fB;
        const half2* sh0 = (const half2*)&s0; const half2* sh1 = (const half2*)&s1;
        const half2* th0 = (const half2*)&t0; const half2* th1 = (const half2*)&t1;

        float a = 0.f, cs = 0.f, ct = 0.f;
#pragma unroll
        for (int j = 0; j < 4; j++) {
            float2 f0 = __half22float2(h2a[j]);
            float2 f1 = __half22float2(h2b[j]);
            a += f0.x * s_as[kb + 2 * j]     + f0.y * s_as[kb + 2 * j + 1];
            a += f1.x * s_as[kb + 8 + 2 * j] + f1.y * s_as[kb + 8 + 2 * j + 1];
            float2 v0 = __half22float2(sh0[j]);
            float2 v1 = __half22float2(sh1[j]);
            cs += v0.x * s_sd[d0 + 2 * j]     + v0.y * s_sd[d0 + 2 * j + 1];
            cs += v1.x * s_sd[d0 + 8 + 2 * j] + v1.y * s_sd[d0 + 8 + 2 * j + 1];
            float2 w0 = __half22float2(th0[j]);
            float2 w1 = __half22float2(th1[j]);
            ct += w0.x * s_td[d0 + 2 * j]     + w0.y * s_td[d0 + 2 * j + 1];
            ct += w1.x * s_td[d0 + 8 + 2 * j] + w1.y * s_td[d0 + 8 + 2 * j + 1];
        }
        a  += __shfl_xor_sync(0xffffffffu, a, 1);
        cs += __shfl_xor_sync(0xffffffffu, cs, 1);
        ct += __shfl_xor_sync(0xffffffffu, ct, 1);
        a  += __shfl_xor_sync(0xffffffffu, a, 2);
        cs += __shfl_xor_sync(0xffffffffu, cs, 2);
        ct += __shfl_xor_sync(0xffffffffu, ct, 2);

        float sim = (TAOV * cs + (1.f - TAOV) * ct + 1.f) * 0.5f;
        float ev = sim * a * etw;
        float ex = __expf(ev);        // |ev| << 88: shift-free softmax is exact
        dsum += ex;

        float exs = ex * snm, ext = ex * tnm;
#pragma unroll
        for (int j = 0; j < 4; j++) {
            float2 f0 = __half22float2(h2a[j]);
            accR[2 * j]     += ex * f0.x;
            accR[2 * j + 1] += ex * f0.y;
            float2 f1 = __half22float2(h2b[j]);
            accR[8 + 2 * j]     += ex * f1.x;
            accR[8 + 2 * j + 1] += ex * f1.y;
            float2 v0 = __half22float2(sh0[j]);
            accS[2 * j]     += exs * v0.x;
            accS[2 * j + 1] += exs * v0.y;
            float2 v1 = __half22float2(sh1[j]);
            accS[8 + 2 * j]     += exs * v1.x;
            accS[8 + 2 * j + 1] += exs * v1.y;
            float2 w0 = __half22float2(th0[j]);
            accT[2 * j]     += ext * w0.x;
            accT[2 * j + 1] += ext * w0.y;
            float2 w1 = __half22float2(th1[j]);
            accT[8 + 2 * j]     += ext * w1.x;
            accT[8 + 2 * j + 1] += ext * w1.y;
        }

        packed = pn; fA = nA; fB = nB; snm = nsn; tnm = ntn;
        i = inext;
    }

    if (q == 0) atomicAdd(&s_den[h], dsum);
#pragma unroll
    for (int k = 0; k < 16; k++) {
        atomicAdd(&s_accR[kb + k], accR[k]);
        atomicAdd(&s_accS[kb + k], accS[k]);
        atomicAdd(&s_accT[kb + k], accT[k]);
    }
    __syncthreads();

    if (tid < 64) {
        int d = tid;
        float rsum = 0.f, ssum = 0.f, tsum = 0.f;
#pragma unroll
        for (int hh = 0; hh < 8; hh++) {
            float den = s_den[hh];
            float inv = (den > 0.f) ? (1.f / den) : 0.f;
            float r = s_accR[hh * 64 + d] * inv + g_res[n * 512 + hh * 64 + d];
            rsum += fmaxf(r, 0.f);
            ssum += s_accS[hh * 64 + d] * inv;
            tsum += s_accT[hh * 64 + d] * inv;
        }
        out[n * 64 + d]               = rsum * 0.125f;
        out[NN * 64 + n * 64 + d]     = sloc[n * 64 + d] + ssum * 0.125f;
        out[2 * NN * 64 + n * 64 + d] = topo[n * 64 + d] + tsum * 0.125f;
    }
}

// ------------------- launch (k_gemm kept in profile slot 4) -------------------
extern "C" void kernel_launch(void* const* d_in, const int* in_sizes, int n_in,
                              void* d_out, int out_size) {
    const float* feat  = (const float*)d_in[0];
    const float* sloc  = (const float*)d_in[1];
    const float* topo  = (const float*)d_in[2];
    const float* Wp    = (const float*)d_in[3];
    const float* Wr    = (const float*)d_in[4];
    const float* Wprob = (const float*)d_in[5];
    const float* etw   = (const float*)d_in[6];
    const int*   src   = (const int*)d_in[7];
    const int*   dst   = (const int*)d_in[8];
    const int*   ef    = (const int*)d_in[9];
    float* out = (float*)d_out;
    int E = in_sizes[7];
    if (E > EMAX) E = EMAX;

    k_zero<<<7, 256>>>();                                   // 1
    k_cvt<<<dim3(49, 16, 5), dim3(32, 8)>>>(feat, Wp, Wr);  // 2
    k_hist<<<(E + 255) / 256, 256>>>(dst, E);               // 3
    k_gemm<<<dim3(16, 13), 256>>>();                        // 4  <- ncu target
    k_rownorm<<<(NN + 3) / 4, 128>>>(sloc, topo);           // 5
    k_attn<<<128, 256>>>(Wprob);                            // 6
    k_scan<<<1, 512>>>();                                   // 7
    k_scatter<<<(E + 255) / 256, 256>>>(dst, src, ef, E);   // 8
    k_edge<<<NN, 256>>>(sloc, topo, etw, out);              // 9
}

// round 13
// speedup vs baseline: 1.1955x; 1.0344x over previous
#include <cuda_runtime.h>
#include <cuda_fp16.h>
#include <cstdint>

#define NN   1546
#define ND   1373
#define KF   1546
#define KP   1568          // padded K (halves), 16B-aligned rows
#define HEADS 8
#define EMAX 210000
#define EPSV 1e-12f
#define TAOV 0.4f

// ------------------- scratch (device globals; no allocs allowed) -------------------
__device__ __align__(16) __half g_f16 [NN * KP];        // feat fp16, padded
__device__ __align__(16) __half g_w16 [4 * 512 * KP];   // W transposed [mat*2+g][n][k] fp16
__device__ __align__(16) __half g_fs16[NN * 512];       // feat_src fp16
__device__ __align__(16) float  g_res [NN * 512];       // resval fp32
__device__ __align__(16) float  g_attn[NN * 512];
__device__ __align__(16) __half g_slt16[NN * 128];      // [sloc raw fp16 (64) | topo raw fp16 (64)]
__device__ __align__(8)  float2 g_inv[NN];              // (1/|sloc|, 1/|topo|)
__device__ float g_colsq [512];
__device__ int   g_cnt[NN];
__device__ int   g_off[NN];
__device__ int   g_cur[NN];
__device__ int   g_ssrc[EMAX];    // sorted: src | (efeat<<16)

// ------------------- helpers -------------------
__device__ __forceinline__ void mma_f16(float* c, const uint32_t* a, const uint32_t* b) {
    asm volatile(
        "mma.sync.aligned.m16n8k16.row.col.f32.f16.f16.f32 "
        "{%0,%1,%2,%3}, {%4,%5,%6,%7}, {%8,%9}, {%0,%1,%2,%3};\n"
        : "+f"(c[0]), "+f"(c[1]), "+f"(c[2]), "+f"(c[3])
        : "r"(a[0]), "r"(a[1]), "r"(a[2]), "r"(a[3]), "r"(b[0]), "r"(b[1]));
}
__device__ __forceinline__ void ldmx4(uint32_t& r0, uint32_t& r1, uint32_t& r2, uint32_t& r3,
                                      uint32_t addr) {
    asm volatile("ldmatrix.sync.aligned.m8n8.x4.shared.b16 {%0,%1,%2,%3}, [%4];"
                 : "=r"(r0), "=r"(r1), "=r"(r2), "=r"(r3) : "r"(addr));
}

// ------------------- zero scratch counters -------------------
__global__ void k_zero() {
    int i = blockIdx.x * 256 + threadIdx.x;
    if (i < NN)  g_cnt[i] = 0;
    if (i < 512) g_colsq[i] = 0.f;
}

// ------ fused prep: W transpose-cvt (z<4), feat cvt (z==4), rownorm (z==5), hist (z==6) ------
__global__ __launch_bounds__(256) void k_prep(const float* __restrict__ feat,
                                              const float* __restrict__ Wp,
                                              const float* __restrict__ Wr,
                                              const float* __restrict__ sloc,
                                              const float* __restrict__ topo,
                                              const int* __restrict__ dst, int E) {
    int z = blockIdx.z;
    int tx = threadIdx.x, ty = threadIdx.y;
    if (z < 4) {
        __shared__ float t[32][33];
        int m = z >> 1, g = z & 1;
        const float* src = (m ? Wr : Wp) + (size_t)g * KF * 512;
        int k0 = blockIdx.x * 32, n0 = blockIdx.y * 32;
#pragma unroll
        for (int i = 0; i < 32; i += 8) {
            int k = k0 + ty + i;
            t[ty + i][tx] = (k < KF) ? src[(size_t)k * 512 + n0 + tx] : 0.f;
        }
        __syncthreads();
#pragma unroll
        for (int i = 0; i < 32; i += 8) {
            int n = n0 + ty + i;
            g_w16[(size_t)(z * 512 + n) * KP + k0 + tx] = __float2half_rn(t[tx][ty + i]);
        }
    } else if (z == 4) {
        int tid = (blockIdx.y * 49 + blockIdx.x) * 256 + ty * 32 + tx;
        int total = NN * KP;
        for (int idx = tid; idx < total; idx += 49 * 16 * 256) {
            int r = idx / KP, c = idx - r * KP;
            g_f16[idx] = (c < KF) ? __float2half_rn(feat[(size_t)r * KF + c]) : __float2half_rn(0.f);
        }
    } else if (z == 5) {
        // rownorm: warp per node, raw fp16 rows + inverse norms
        int n = (blockIdx.y * 49 + blockIdx.x) * 8 + ty;
        if (n >= NN) return;
        int lane = tx;
        float2 sv = *(const float2*)(sloc + (size_t)n * 64 + 2 * lane);
        float2 tv = *(const float2*)(topo + (size_t)n * 64 + 2 * lane);
        float ss = sv.x * sv.x + sv.y * sv.y;
        float tt = tv.x * tv.x + tv.y * tv.y;
#pragma unroll
        for (int off = 16; off; off >>= 1) {
            ss += __shfl_xor_sync(0xffffffffu, ss, off);
            tt += __shfl_xor_sync(0xffffffffu, tt, off);
        }
        float si = 1.f / fmaxf(sqrtf(ss), EPSV);
        float ti = 1.f / fmaxf(sqrtf(tt), EPSV);
        ((half2*)(g_slt16 + (size_t)n * 128))[lane]      = __floats2half2_rn(sv.x, sv.y);
        ((half2*)(g_slt16 + (size_t)n * 128))[lane + 32] = __floats2half2_rn(tv.x, tv.y);
        if (lane == 0) g_inv[n] = make_float2(si, ti);
    } else {
        // hist
        int e = (blockIdx.y * 49 + blockIdx.x) * 256 + ty * 32 + tx;
        for (; e < E; e += 49 * 16 * 256)
            atomicAdd(&g_cnt[dst[e]], 1);
    }
}

// ------------------- scan (offsets only) -------------------
__global__ __launch_bounds__(512) void k_scan() {
    __shared__ int sh[512];
    int t = threadIdx.x;
    int base = t * 4;
    int v0 = (base     < NN) ? g_cnt[base]     : 0;
    int v1 = (base + 1 < NN) ? g_cnt[base + 1] : 0;
    int v2 = (base + 2 < NN) ? g_cnt[base + 2] : 0;
    int v3 = (base + 3 < NN) ? g_cnt[base + 3] : 0;
    int p0 = v0, p1 = p0 + v1, p2 = p1 + v2, p3 = p2 + v3;
    sh[t] = p3;
    __syncthreads();
    for (int off = 1; off < 512; off <<= 1) {
        int x = 0;
        if (t >= off) x = sh[t - off];
        __syncthreads();
        sh[t] += x;
        __syncthreads();
    }
    int excl = sh[t] - p3;
    if (base     < NN) { g_off[base]     = excl;      g_cur[base]     = excl; }
    if (base + 1 < NN) { g_off[base + 1] = excl + p0; g_cur[base + 1] = excl + p0; }
    if (base + 2 < NN) { g_off[base + 2] = excl + p1; g_cur[base + 2] = excl + p1; }
    if (base + 3 < NN) { g_off[base + 3] = excl + p2; g_cur[base + 3] = excl + p2; }
}

// ------------- fp16 GEMM: BM=128 BN=64 BK=32, 256 thr, 2 CTA/SM, fp16 staging -------------
#define APADH 40
#define BPADH 40

__device__ __forceinline__ void ldA4(int rowb, int rowEnd, int k0, int tid, int4* pa) {
#pragma unroll
    for (int j = 0; j < 2; j++) {
        int idx = tid + j * 256;
        int r = idx >> 2, c = idx & 3;
        int gr = rowb + r;
        int4 v = make_int4(0, 0, 0, 0);
        if (gr < rowEnd) v = *(const int4*)(g_f16 + (size_t)gr * KP + k0 + c * 8);
        pa[j] = v;
    }
}
__device__ __forceinline__ void ldB4(const __half* Wb, int k0, int tid, int4* pb) {
    int n = tid >> 2, c = tid & 3;
    pb[0] = *(const int4*)(Wb + (size_t)n * KP + k0 + c * 8);
}
__device__ __forceinline__ void stA4(__half* As, int tid, const int4* pa) {
#pragma unroll
    for (int j = 0; j < 2; j++) {
        int idx = tid + j * 256;
        int r = idx >> 2, c = idx & 3;
        *(int4*)(As + r * APADH + c * 8) = pa[j];
    }
}
__device__ __forceinline__ void stB4(__half* Bs, int tid, const int4* pb) {
    int n = tid >> 2, c = tid & 3;
    *(int4*)(Bs + n * BPADH + c * 8) = pb[0];
}

__global__ __launch_bounds__(256, 2) void k_gemm() {
    __shared__ __align__(16) __half As[2][128 * APADH];
    __shared__ __align__(16) __half Bs[2][64 * BPADH];
    int tid = threadIdx.x, lane = tid & 31, warp = tid >> 5;
    int by = blockIdx.y, bx = blockIdx.x;

    int g, rowb, rowEnd;
    if (by < 11) { g = 0; rowb = by * 128; rowEnd = ND; }
    else         { g = 1; rowb = ND + (by - 11) * 128; rowEnd = NN; }

    int cb0 = bx * 64;
    int colb;
    bool isFs;
    int m;
    if (cb0 < 512) { m = 0; colb = cb0;       isFs = true; }
    else           { m = 1; colb = cb0 - 512; isFs = false; }
    const __half* Wb = g_w16 + (size_t)((m * 2 + g) * 512 + colb) * KP;

    float c[2][4][4];
#pragma unroll
    for (int i = 0; i < 2; i++)
#pragma unroll
        for (int j = 0; j < 4; j++)
#pragma unroll
            for (int k = 0; k < 4; k++) c[i][j][k] = 0.f;

    int4 pa[2], pb[1];
    ldA4(rowb, rowEnd, 0, tid, pa);
    ldB4(Wb, 0, tid, pb);
    stA4(As[0], tid, pa);
    stB4(Bs[0], tid, pb);
    __syncthreads();

    int p = 0;
    int warpM = warp >> 1, warpN = warp & 1;
    int l8 = lane & 7, grp = lane >> 3;
    int aRowOff = warpM * 32 + ((grp & 1) << 3) + l8;
    int aKOff   = (grp >> 1) << 3;
    int bNOff   = warpN * 32 + ((grp >> 1) << 3) + l8;
    int bKOff   = (grp & 1) << 3;

    for (int k0 = 0; k0 < KF; k0 += 32) {
        int kn = k0 + 32;
        if (kn < KF) { ldA4(rowb, rowEnd, kn, tid, pa); ldB4(Wb, kn, tid, pb); }

        uint32_t a_base = (uint32_t)__cvta_generic_to_shared(&As[p][0]);
        uint32_t b_base = (uint32_t)__cvta_generic_to_shared(&Bs[p][0]);
#pragma unroll
        for (int kk = 0; kk < 32; kk += 16) {
            uint32_t af[2][4], bf[4][2];
#pragma unroll
            for (int mt = 0; mt < 2; mt++) {
                uint32_t addr = a_base + (uint32_t)(((aRowOff + mt * 16) * APADH + kk + aKOff) * 2);
                ldmx4(af[mt][0], af[mt][1], af[mt][2], af[mt][3], addr);
            }
#pragma unroll
            for (int pr = 0; pr < 2; pr++) {
                uint32_t addr = b_base + (uint32_t)(((bNOff + pr * 16) * BPADH + kk + bKOff) * 2);
                ldmx4(bf[2 * pr][0], bf[2 * pr][1], bf[2 * pr + 1][0], bf[2 * pr + 1][1], addr);
            }
#pragma unroll
            for (int mt = 0; mt < 2; mt++)
#pragma unroll
                for (int nt = 0; nt < 4; nt++)
                    mma_f16(c[mt][nt], af[mt], bf[nt]);
        }

        if (kn < KF) {
            stA4(As[p ^ 1], tid, pa);
            stB4(Bs[p ^ 1], tid, pb);
            __syncthreads();
            p ^= 1;
        }
    }

#pragma unroll
    for (int mt = 0; mt < 2; mt++) {
        int row0 = rowb + warpM * 32 + mt * 16 + (lane >> 2);
#pragma unroll
        for (int nt = 0; nt < 4; nt++) {
            int col = colb + warpN * 32 + nt * 8 + (lane & 3) * 2;
            if (isFs) {
                if (row0 < rowEnd)
                    *(half2*)(g_fs16 + (size_t)row0 * 512 + col) = __floats2half2_rn(c[mt][nt][0], c[mt][nt][1]);
                if (row0 + 8 < rowEnd)
                    *(half2*)(g_fs16 + (size_t)(row0 + 8) * 512 + col) = __floats2half2_rn(c[mt][nt][2], c[mt][nt][3]);
            } else {
                if (row0 < rowEnd)
                    *(float2*)(g_res + (size_t)row0 * 512 + col) = make_float2(c[mt][nt][0], c[mt][nt][1]);
                if (row0 + 8 < rowEnd)
                    *(float2*)(g_res + (size_t)(row0 + 8) * 512 + col) = make_float2(c[mt][nt][2], c[mt][nt][3]);
            }
        }
    }
}

// -------- fused attn (blocks 0..127) + scatter (blocks 128..911) --------
#define ATTN_CH 97
__global__ __launch_bounds__(256) void k_as(const float* __restrict__ Wprob,
                                            const int* __restrict__ dst,
                                            const int* __restrict__ src,
                                            const int* __restrict__ efeat, int E) {
    int tid = threadIdx.x;
    if (blockIdx.x >= 128) {
        int e = (blockIdx.x - 128) * 256 + tid;
        for (; e < E; e += 784 * 256) {
            int pos = atomicAdd(&g_cur[dst[e]], 1);
            g_ssrc[pos] = src[e] | (efeat[e] << 16);
        }
        return;
    }
    __shared__ float Wh[4096];
    __shared__ float fsh[8][64];
    __shared__ float s_csq[64];
    int warp = tid >> 5, lane = tid & 31;
    int h = blockIdx.x & 7, chunk = blockIdx.x >> 3;
    const float* W = Wprob + h * 4096;
    for (int i = tid; i < 4096; i += 256) Wh[i] = W[i];
    if (tid < 64) s_csq[tid] = 0.f;
    __syncthreads();

    float sq0 = 0.f, sq1 = 0.f;
    int n0 = chunk * ATTN_CH;
    int n1 = min(n0 + ATTN_CH, NN);
    for (int n = n0 + warp; n < n1; n += 8) {
        float v0 = __half2float(g_fs16[n * 512 + h * 64 + lane]);
        float v1 = __half2float(g_fs16[n * 512 + h * 64 + lane + 32]);
        fsh[warp][lane]      = v0;
        fsh[warp][lane + 32] = v1;
        sq0 += v0 * v0;
        sq1 += v1 * v1;
        __syncwarp();
        float a0 = 0.f, a1 = 0.f;
#pragma unroll 8
        for (int d = 0; d < 64; d++) {
            float f = fsh[warp][d];
            a0 += f * Wh[d * 64 + lane];
            a1 += f * Wh[d * 64 + lane + 32];
        }
        float t0 = tanhf(a0), t1 = tanhf(a1);
        float m = fmaxf(t0, t1);
#pragma unroll
        for (int off = 16; off; off >>= 1) m = fmaxf(m, __shfl_xor_sync(0xffffffffu, m, off));
        float e0 = __expf(t0 - m), e1 = __expf(t1 - m);
        float s = e0 + e1;
#pragma unroll
        for (int off = 16; off; off >>= 1) s += __shfl_xor_sync(0xffffffffu, s, off);
        float inv = 1.f / s;
        g_attn[n * 512 + h * 64 + lane]      = e0 * inv;
        g_attn[n * 512 + h * 64 + lane + 32] = e1 * inv;
        __syncwarp();
    }
    atomicAdd(&s_csq[lane], sq0);
    atomicAdd(&s_csq[lane + 32], sq1);
    __syncthreads();
    if (tid < 64) atomicAdd(&g_colsq[h * 64 + tid], s_csq[tid]);
}

// ----- edge phase: shift-free softmax, raw combined slt rows, inline rscale -----
__global__ __launch_bounds__(256, 2) void k_edge(const float* __restrict__ sloc,
                                                 const float* __restrict__ topo,
                                                 const float* __restrict__ etw_tab,
                                                 float* __restrict__ out) {
    __shared__ float s_as[512];
    __shared__ float s_sd[64], s_td[64];
    __shared__ float s_accR[512], s_accS[512], s_accT[512];
    __shared__ float s_den[8], s_etw[4];

    int n = blockIdx.x;
    int tid = threadIdx.x, warp = tid >> 5, lane = tid & 31;
    int start = g_off[n], cnt = g_cnt[n];

    for (int i = tid; i < 512; i += 256) {
        s_as[i] = g_attn[n * 512 + i] / fmaxf(sqrtf(g_colsq[i]), EPSV);
        s_accR[i] = 0.f; s_accS[i] = 0.f; s_accT[i] = 0.f;
    }
    if (tid < 64) {
        float2 iv = g_inv[n];
        s_sd[tid] = __half2float(g_slt16[n * 128 + tid]) * iv.x;
        s_td[tid] = __half2float(g_slt16[n * 128 + 64 + tid]) * iv.y;
    }
    if (tid < 8) s_den[tid] = 0.f;
    if (tid < 4) s_etw[tid] = etw_tab[tid];
    __syncthreads();

    int h = lane >> 2, q = lane & 3;
    int kb = lane * 16, d0 = q * 16;
    float dsum = 0.f;
    float accR[16], accS[16], accT[16];
#pragma unroll
    for (int k = 0; k < 16; k++) { accR[k] = 0.f; accS[k] = 0.f; accT[k] = 0.f; }

    // prefetch pipeline
    int i = warp;
    int packed = 0;
    int4 fA = make_int4(0, 0, 0, 0), fB = fA;
    float2 iv = make_float2(0.f, 0.f);
    if (i < cnt) {
        packed = g_ssrc[start + i];
        int s0i = packed & 0xFFFF;
        const int4* fp = (const int4*)(g_fs16 + (size_t)s0i * 512 + kb);
        fA = fp[0]; fB = fp[1];
        iv = g_inv[s0i];
    }

    while (i < cnt) {
        int s = packed & 0xFFFF;
        float etw = s_etw[packed >> 16];

        const int4* sp = (const int4*)(g_slt16 + (size_t)s * 128 + d0);
        int4 s0 = sp[0], s1 = sp[1];       // sloc raw chunk
        int4 t0 = sp[8], t1 = sp[9];       // topo raw chunk (+64 halves = +8 int4)

        int inext = i + 8;
        int pn = packed;
        int4 nA = fA, nB = fB;
        float2 niv = iv;
        if (inext < cnt) {
            pn = g_ssrc[start + inext];
            int sn_ = pn & 0xFFFF;
            const int4* fpn = (const int4*)(g_fs16 + (size_t)sn_ * 512 + kb);
            nA = fpn[0]; nB = fpn[1];
            niv = g_inv[sn_];
        }

        const half2* h2a = (const half2*)&fA;
        const half2* h2b = (const half2*)&fB;
        const half2* sh0 = (const half2*)&s0; const half2* sh1 = (const half2*)&s1;
        const half2* th0 = (const half2*)&t0; const half2* th1 = (const half2*)&t1;

        float a = 0.f, cs = 0.f, ct = 0.f;
#pragma unroll
        for (int j = 0; j < 4; j++) {
            float2 f0 = __half22float2(h2a[j]);
            float2 f1 = __half22float2(h2b[j]);
            a += f0.x * s_as[kb + 2 * j]     + f0.y * s_as[kb + 2 * j + 1];
            a += f1.x * s_as[kb + 8 + 2 * j] + f1.y * s_as[kb + 8 + 2 * j + 1];
            float2 v0 = __half22float2(sh0[j]);
            float2 v1 = __half22float2(sh1[j]);
            cs += v0.x * s_sd[d0 + 2 * j]     + v0.y * s_sd[d0 + 2 * j + 1];
            cs += v1.x * s_sd[d0 + 8 + 2 * j] + v1.y * s_sd[d0 + 8 + 2 * j + 1];
            float2 w0 = __half22float2(th0[j]);
            float2 w1 = __half22float2(th1[j]);
            ct += w0.x * s_td[d0 + 2 * j]     + w0.y * s_td[d0 + 2 * j + 1];
            ct += w1.x * s_td[d0 + 8 + 2 * j] + w1.y * s_td[d0 + 8 + 2 * j + 1];
        }
        a  += __shfl_xor_sync(0xffffffffu, a, 1);
        cs += __shfl_xor_sync(0xffffffffu, cs, 1);
        ct += __shfl_xor_sync(0xffffffffu, ct, 1);
        a  += __shfl_xor_sync(0xffffffffu, a, 2);
        cs += __shfl_xor_sync(0xffffffffu, cs, 2);
        ct += __shfl_xor_sync(0xffffffffu, ct, 2);
        cs *= iv.x;
        ct *= iv.y;

        float sim = (TAOV * cs + (1.f - TAOV) * ct + 1.f) * 0.5f;
        float ev = sim * a * etw;
        float ex = __expf(ev);
        dsum += ex;

#pragma unroll
        for (int j = 0; j < 4; j++) {
            float2 f0 = __half22float2(h2a[j]);
            accR[2 * j]     += ex * f0.x;
            accR[2 * j + 1] += ex * f0.y;
            float2 f1 = __half22float2(h2b[j]);
            accR[8 + 2 * j]     += ex * f1.x;
            accR[8 + 2 * j + 1] += ex * f1.y;
            float2 v0 = __half22float2(sh0[j]);
            accS[2 * j]     += ex * v0.x;
            accS[2 * j + 1] += ex * v0.y;
            float2 v1 = __half22float2(sh1[j]);
            accS[8 + 2 * j]     += ex * v1.x;
            accS[8 + 2 * j + 1] += ex * v1.y;
            float2 w0 = __half22float2(th0[j]);
            accT[2 * j]     += ex * w0.x;
            accT[2 * j + 1] += ex * w0.y;
            float2 w1 = __half22float2(th1[j]);
            accT[8 + 2 * j]     += ex * w1.x;
            accT[8 + 2 * j + 1] += ex * w1.y;
        }

        packed = pn; fA = nA; fB = nB; iv = niv;
        i = inext;
    }

    if (q == 0) atomicAdd(&s_den[h], dsum);
#pragma unroll
    for (int k = 0; k < 16; k++) {
        atomicAdd(&s_accR[kb + k], accR[k]);
        atomicAdd(&s_accS[kb + k], accS[k]);
        atomicAdd(&s_accT[kb + k], accT[k]);
    }
    __syncthreads();

    if (tid < 64) {
        int d = tid;
        float rsum = 0.f, ssum = 0.f, tsum = 0.f;
#pragma unroll
        for (int hh = 0; hh < 8; hh++) {
            float den = s_den[hh];
            float inv = (den > 0.f) ? (1.f / den) : 0.f;
            float r = s_accR[hh * 64 + d] * inv + g_res[n * 512 + hh * 64 + d];
            rsum += fmaxf(r, 0.f);
            ssum += s_accS[hh * 64 + d] * inv;
            tsum += s_accT[hh * 64 + d] * inv;
        }
        out[n * 64 + d]               = rsum * 0.125f;
        out[NN * 64 + n * 64 + d]     = sloc[n * 64 + d] + ssum * 0.125f;
        out[2 * NN * 64 + n * 64 + d] = topo[n * 64 + d] + tsum * 0.125f;
    }
}

// ------------------- launch: 6 launches, k_gemm in profile slot 4 -------------------
extern "C" void kernel_launch(void* const* d_in, const int* in_sizes, int n_in,
                              void* d_out, int out_size) {
    const float* feat  = (const float*)d_in[0];
    const float* sloc  = (const float*)d_in[1];
    const float* topo  = (const float*)d_in[2];
    const float* Wp    = (const float*)d_in[3];
    const float* Wr    = (const float*)d_in[4];
    const float* Wprob = (const float*)d_in[5];
    const float* etw   = (const float*)d_in[6];
    const int*   src   = (const int*)d_in[7];
    const int*   dst   = (const int*)d_in[8];
    const int*   ef    = (const int*)d_in[9];
    float* out = (float*)d_out;
    int E = in_sizes[7];
    if (E > EMAX) E = EMAX;

    k_zero<<<7, 256>>>();                                           // 1
    k_prep<<<dim3(49, 16, 7), dim3(32, 8)>>>(feat, Wp, Wr, sloc, topo, dst, E); // 2
    k_scan<<<1, 512>>>();                                           // 3
    k_gemm<<<dim3(16, 13), 256>>>();                                // 4  <- ncu target
    k_as<<<912, 256>>>(Wprob, dst, src, ef, E);                     // 5
    k_edge<<<NN, 256>>>(sloc, topo, etw, out);                      // 6
}

// round 14
// speedup vs baseline: 1.2088x; 1.0111x over previous
#include <cuda_runtime.h>
#include <cuda_fp16.h>
#include <cstdint>

#define NN   1546
#define ND   1373
#define KF   1546
#define KP   1568          // padded K (halves), 16B-aligned rows
#define HEADS 8
#define EMAX 210000
#define EPSV 1e-12f
#define TAOV 0.4f

typedef unsigned long long ull;

// ------------------- scratch (device globals; no allocs allowed) -------------------
__device__ __align__(16) __half g_f16 [NN * KP];        // feat fp16, padded
__device__ __align__(16) __half g_w16 [4 * 512 * KP];   // W transposed [mat*2+g][n][k] fp16
__device__ __align__(16) __half g_fs16[NN * 512];       // feat_src fp16
__device__ __align__(16) float  g_res [NN * 512];       // resval fp32
__device__ __align__(16) float  g_attn[NN * 512];
__device__ __align__(16) __half g_slt16[NN * 128];      // [sloc raw fp16 (64) | topo raw fp16 (64)]
__device__ __align__(8)  float2 g_inv[NN];              // (1/|sloc|, 1/|topo|)
__device__ float g_colsq [512];
__device__ int   g_cnt[NN];
__device__ int   g_off[NN];
__device__ int   g_cur[NN];
__device__ int   g_ssrc[EMAX];    // sorted: src | (efeat<<16)

// ------------------- helpers -------------------
__device__ __forceinline__ void mma_f16(float* c, const uint32_t* a, const uint32_t* b) {
    asm volatile(
        "mma.sync.aligned.m16n8k16.row.col.f32.f16.f16.f32 "
        "{%0,%1,%2,%3}, {%4,%5,%6,%7}, {%8,%9}, {%0,%1,%2,%3};\n"
        : "+f"(c[0]), "+f"(c[1]), "+f"(c[2]), "+f"(c[3])
        : "r"(a[0]), "r"(a[1]), "r"(a[2]), "r"(a[3]), "r"(b[0]), "r"(b[1]));
}
__device__ __forceinline__ void ldmx4(uint32_t& r0, uint32_t& r1, uint32_t& r2, uint32_t& r3,
                                      uint32_t addr) {
    asm volatile("ldmatrix.sync.aligned.m8n8.x4.shared.b16 {%0,%1,%2,%3}, [%4];"
                 : "=r"(r0), "=r"(r1), "=r"(r2), "=r"(r3) : "r"(addr));
}
// packed f32x2 helpers (sm_100+)
__device__ __forceinline__ ull pkf2(float x, float y) {
    ull r; asm("mov.b64 %0, {%1, %2};" : "=l"(r) : "f"(x), "f"(y)); return r;
}
__device__ __forceinline__ void upkf2(ull a, float& x, float& y) {
    asm("mov.b64 {%0, %1}, %2;" : "=f"(x), "=f"(y) : "l"(a));
}
__device__ __forceinline__ void fma2p(ull& d, ull a, ull b) {
    asm("fma.rn.f32x2 %0, %1, %2, %3;" : "=l"(d) : "l"(a), "l"(b), "l"(d));
}
__device__ __forceinline__ ull h2p(half2 h) {
    float2 v = __half22float2(h);
    return pkf2(v.x, v.y);
}

// ------------------- zero scratch counters -------------------
__global__ void k_zero() {
    int i = blockIdx.x * 256 + threadIdx.x;
    if (i < NN)  g_cnt[i] = 0;
    if (i < 512) g_colsq[i] = 0.f;
}

// ------ fused prep: W transpose-cvt (z<4), feat cvt (z==4), rownorm (z==5), hist (z==6) ------
__global__ __launch_bounds__(256) void k_prep(const float* __restrict__ feat,
                                              const float* __restrict__ Wp,
                                              const float* __restrict__ Wr,
                                              const float* __restrict__ sloc,
                                              const float* __restrict__ topo,
                                              const int* __restrict__ dst, int E) {
    int z = blockIdx.z;
    int tx = threadIdx.x, ty = threadIdx.y;
    if (z < 4) {
        __shared__ float t[32][33];
        int m = z >> 1, g = z & 1;
        const float* src = (m ? Wr : Wp) + (size_t)g * KF * 512;
        int k0 = blockIdx.x * 32, n0 = blockIdx.y * 32;
#pragma unroll
        for (int i = 0; i < 32; i += 8) {
            int k = k0 + ty + i;
            t[ty + i][tx] = (k < KF) ? src[(size_t)k * 512 + n0 + tx] : 0.f;
        }
        __syncthreads();
#pragma unroll
        for (int i = 0; i < 32; i += 8) {
            int n = n0 + ty + i;
            g_w16[(size_t)(z * 512 + n) * KP + k0 + tx] = __float2half_rn(t[tx][ty + i]);
        }
    } else if (z == 4) {
        int tid = (blockIdx.y * 49 + blockIdx.x) * 256 + ty * 32 + tx;
        int total = NN * KP;
        for (int idx = tid; idx < total; idx += 49 * 16 * 256) {
            int r = idx / KP, c = idx - r * KP;
            g_f16[idx] = (c < KF) ? __float2half_rn(feat[(size_t)r * KF + c]) : __float2half_rn(0.f);
        }
    } else if (z == 5) {
        int n = (blockIdx.y * 49 + blockIdx.x) * 8 + ty;
        if (n >= NN) return;
        int lane = tx;
        float2 sv = *(const float2*)(sloc + (size_t)n * 64 + 2 * lane);
        float2 tv = *(const float2*)(topo + (size_t)n * 64 + 2 * lane);
        float ss = sv.x * sv.x + sv.y * sv.y;
        float tt = tv.x * tv.x + tv.y * tv.y;
#pragma unroll
        for (int off = 16; off; off >>= 1) {
            ss += __shfl_xor_sync(0xffffffffu, ss, off);
            tt += __shfl_xor_sync(0xffffffffu, tt, off);
        }
        float si = 1.f / fmaxf(sqrtf(ss), EPSV);
        float ti = 1.f / fmaxf(sqrtf(tt), EPSV);
        ((half2*)(g_slt16 + (size_t)n * 128))[lane]      = __floats2half2_rn(sv.x, sv.y);
        ((half2*)(g_slt16 + (size_t)n * 128))[lane + 32] = __floats2half2_rn(tv.x, tv.y);
        if (lane == 0) g_inv[n] = make_float2(si, ti);
    } else {
        int e = (blockIdx.y * 49 + blockIdx.x) * 256 + ty * 32 + tx;
        for (; e < E; e += 49 * 16 * 256)
            atomicAdd(&g_cnt[dst[e]], 1);
    }
}

// ------------------- scan (offsets only) -------------------
__global__ __launch_bounds__(512) void k_scan() {
    __shared__ int sh[512];
    int t = threadIdx.x;
    int base = t * 4;
    int v0 = (base     < NN) ? g_cnt[base]     : 0;
    int v1 = (base + 1 < NN) ? g_cnt[base + 1] : 0;
    int v2 = (base + 2 < NN) ? g_cnt[base + 2] : 0;
    int v3 = (base + 3 < NN) ? g_cnt[base + 3] : 0;
    int p0 = v0, p1 = p0 + v1, p2 = p1 + v2, p3 = p2 + v3;
    sh[t] = p3;
    __syncthreads();
    for (int off = 1; off < 512; off <<= 1) {
        int x = 0;
        if (t >= off) x = sh[t - off];
        __syncthreads();
        sh[t] += x;
        __syncthreads();
    }
    int excl = sh[t] - p3;
    if (base     < NN) { g_off[base]     = excl;      g_cur[base]     = excl; }
    if (base + 1 < NN) { g_off[base + 1] = excl + p0; g_cur[base + 1] = excl + p0; }
    if (base + 2 < NN) { g_off[base + 2] = excl + p1; g_cur[base + 2] = excl + p1; }
    if (base + 3 < NN) { g_off[base + 3] = excl + p2; g_cur[base + 3] = excl + p2; }
}

// ------------- fp16 GEMM: BM=128 BN=64 BK=32, 256 thr, 2 CTA/SM, fp16 staging -------------
#define APADH 40
#define BPADH 40

__device__ __forceinline__ void ldA4(int rowb, int rowEnd, int k0, int tid, int4* pa) {
#pragma unroll
    for (int j = 0; j < 2; j++) {
        int idx = tid + j * 256;
        int r = idx >> 2, c = idx & 3;
        int gr = rowb + r;
        int4 v = make_int4(0, 0, 0, 0);
        if (gr < rowEnd) v = *(const int4*)(g_f16 + (size_t)gr * KP + k0 + c * 8);
        pa[j] = v;
    }
}
__device__ __forceinline__ void ldB4(const __half* Wb, int k0, int tid, int4* pb) {
    int n = tid >> 2, c = tid & 3;
    pb[0] = *(const int4*)(Wb + (size_t)n * KP + k0 + c * 8);
}
__device__ __forceinline__ void stA4(__half* As, int tid, const int4* pa) {
#pragma unroll
    for (int j = 0; j < 2; j++) {
        int idx = tid + j * 256;
        int r = idx >> 2, c = idx & 3;
        *(int4*)(As + r * APADH + c * 8) = pa[j];
    }
}
__device__ __forceinline__ void stB4(__half* Bs, int tid, const int4* pb) {
    int n = tid >> 2, c = tid & 3;
    *(int4*)(Bs + n * BPADH + c * 8) = pb[0];
}

__global__ __launch_bounds__(256, 2) void k_gemm() {
    __shared__ __align__(16) __half As[2][128 * APADH];
    __shared__ __align__(16) __half Bs[2][64 * BPADH];
    int tid = threadIdx.x, lane = tid & 31, warp = tid >> 5;
    int by = blockIdx.y, bx = blockIdx.x;

    int g, rowb, rowEnd;
    if (by < 11) { g = 0; rowb = by * 128; rowEnd = ND; }
    else         { g = 1; rowb = ND + (by - 11) * 128; rowEnd = NN; }

    int cb0 = bx * 64;
    int colb;
    bool isFs;
    int m;
    if (cb0 < 512) { m = 0; colb = cb0;       isFs = true; }
    else           { m = 1; colb = cb0 - 512; isFs = false; }
    const __half* Wb = g_w16 + (size_t)((m * 2 + g) * 512 + colb) * KP;

    float c[2][4][4];
#pragma unroll
    for (int i = 0; i < 2; i++)
#pragma unroll
        for (int j = 0; j < 4; j++)
#pragma unroll
            for (int k = 0; k < 4; k++) c[i][j][k] = 0.f;

    int4 pa[2], pb[1];
    ldA4(rowb, rowEnd, 0, tid, pa);
    ldB4(Wb, 0, tid, pb);
    stA4(As[0], tid, pa);
    stB4(Bs[0], tid, pb);
    __syncthreads();

    int p = 0;
    int warpM = warp >> 1, warpN = warp & 1;
    int l8 = lane & 7, grp = lane >> 3;
    int aRowOff = warpM * 32 + ((grp & 1) << 3) + l8;
    int aKOff   = (grp >> 1) << 3;
    int bNOff   = warpN * 32 + ((grp >> 1) << 3) + l8;
    int bKOff   = (grp & 1) << 3;

    for (int k0 = 0; k0 < KF; k0 += 32) {
        int kn = k0 + 32;
        if (kn < KF) { ldA4(rowb, rowEnd, kn, tid, pa); ldB4(Wb, kn, tid, pb); }

        uint32_t a_base = (uint32_t)__cvta_generic_to_shared(&As[p][0]);
        uint32_t b_base = (uint32_t)__cvta_generic_to_shared(&Bs[p][0]);
#pragma unroll
        for (int kk = 0; kk < 32; kk += 16) {
            uint32_t af[2][4], bf[4][2];
#pragma unroll
            for (int mt = 0; mt < 2; mt++) {
                uint32_t addr = a_base + (uint32_t)(((aRowOff + mt * 16) * APADH + kk + aKOff) * 2);
                ldmx4(af[mt][0], af[mt][1], af[mt][2], af[mt][3], addr);
            }
#pragma unroll
            for (int pr = 0; pr < 2; pr++) {
                uint32_t addr = b_base + (uint32_t)(((bNOff + pr * 16) * BPADH + kk + bKOff) * 2);
                ldmx4(bf[2 * pr][0], bf[2 * pr][1], bf[2 * pr + 1][0], bf[2 * pr + 1][1], addr);
            }
#pragma unroll
            for (int mt = 0; mt < 2; mt++)
#pragma unroll
                for (int nt = 0; nt < 4; nt++)
                    mma_f16(c[mt][nt], af[mt], bf[nt]);
        }

        if (kn < KF) {
            stA4(As[p ^ 1], tid, pa);
            stB4(Bs[p ^ 1], tid, pb);
            __syncthreads();
            p ^= 1;
        }
    }

#pragma unroll
    for (int mt = 0; mt < 2; mt++) {
        int row0 = rowb + warpM * 32 + mt * 16 + (lane >> 2);
#pragma unroll
        for (int nt = 0; nt < 4; nt++) {
            int col = colb + warpN * 32 + nt * 8 + (lane & 3) * 2;
            if (isFs) {
                if (row0 < rowEnd)
                    *(half2*)(g_fs16 + (size_t)row0 * 512 + col) = __floats2half2_rn(c[mt][nt][0], c[mt][nt][1]);
                if (row0 + 8 < rowEnd)
                    *(half2*)(g_fs16 + (size_t)(row0 + 8) * 512 + col) = __floats2half2_rn(c[mt][nt][2], c[mt][nt][3]);
            } else {
                if (row0 < rowEnd)
                    *(float2*)(g_res + (size_t)row0 * 512 + col) = make_float2(c[mt][nt][0], c[mt][nt][1]);
                if (row0 + 8 < rowEnd)
                    *(float2*)(g_res + (size_t)(row0 + 8) * 512 + col) = make_float2(c[mt][nt][2], c[mt][nt][3]);
            }
        }
    }
}

// -------- fused attn (blocks 0..127) + scatter (blocks 128..911) --------
#define ATTN_CH 97
__global__ __launch_bounds__(256) void k_as(const float* __restrict__ Wprob,
                                            const int* __restrict__ dst,
                                            const int* __restrict__ src,
                                            const int* __restrict__ efeat, int E) {
    int tid = threadIdx.x;
    if (blockIdx.x >= 128) {
        int e = (blockIdx.x - 128) * 256 + tid;
        for (; e < E; e += 784 * 256) {
            int pos = atomicAdd(&g_cur[dst[e]], 1);
            g_ssrc[pos] = src[e] | (efeat[e] << 16);
        }
        return;
    }
    __shared__ float Wh[4096];
    __shared__ float fsh[8][64];
    __shared__ float s_csq[64];
    int warp = tid >> 5, lane = tid & 31;
    int h = blockIdx.x & 7, chunk = blockIdx.x >> 3;
    const float* W = Wprob + h * 4096;
    for (int i = tid; i < 4096; i += 256) Wh[i] = W[i];
    if (tid < 64) s_csq[tid] = 0.f;
    __syncthreads();

    float sq0 = 0.f, sq1 = 0.f;
    int n0 = chunk * ATTN_CH;
    int n1 = min(n0 + ATTN_CH, NN);
    for (int n = n0 + warp; n < n1; n += 8) {
        float v0 = __half2float(g_fs16[n * 512 + h * 64 + lane]);
        float v1 = __half2float(g_fs16[n * 512 + h * 64 + lane + 32]);
        fsh[warp][lane]      = v0;
        fsh[warp][lane + 32] = v1;
        sq0 += v0 * v0;
        sq1 += v1 * v1;
        __syncwarp();
        float a0 = 0.f, a1 = 0.f;
#pragma unroll 8
        for (int d = 0; d < 64; d++) {
            float f = fsh[warp][d];
            a0 += f * Wh[d * 64 + lane];
            a1 += f * Wh[d * 64 + lane + 32];
        }
        float t0 = tanhf(a0), t1 = tanhf(a1);
        float m = fmaxf(t0, t1);
#pragma unroll
        for (int off = 16; off; off >>= 1) m = fmaxf(m, __shfl_xor_sync(0xffffffffu, m, off));
        float e0 = __expf(t0 - m), e1 = __expf(t1 - m);
        float s = e0 + e1;
#pragma unroll
        for (int off = 16; off; off >>= 1) s += __shfl_xor_sync(0xffffffffu, s, off);
        float inv = 1.f / s;
        g_attn[n * 512 + h * 64 + lane]      = e0 * inv;
        g_attn[n * 512 + h * 64 + lane + 32] = e1 * inv;
        __syncwarp();
    }
    atomicAdd(&s_csq[lane], sq0);
    atomicAdd(&s_csq[lane + 32], sq1);
    __syncthreads();
    if (tid < 64) atomicAdd(&g_colsq[h * 64 + tid], s_csq[tid]);
}

// ----- edge phase: shift-free softmax, packed f32x2 math -----
__global__ __launch_bounds__(256, 2) void k_edge(const float* __restrict__ sloc,
                                                 const float* __restrict__ topo,
                                                 const float* __restrict__ etw_tab,
                                                 float* __restrict__ out) {
    __shared__ float s_as[512];
    __shared__ float s_sd[64], s_td[64];
    __shared__ float s_accR[512], s_accS[512], s_accT[512];
    __shared__ float s_den[8], s_etw[4];

    int n = blockIdx.x;
    int tid = threadIdx.x, warp = tid >> 5, lane = tid & 31;
    int start = g_off[n], cnt = g_cnt[n];

    for (int i = tid; i < 512; i += 256) {
        s_as[i] = g_attn[n * 512 + i] / fmaxf(sqrtf(g_colsq[i]), EPSV);
        s_accR[i] = 0.f; s_accS[i] = 0.f; s_accT[i] = 0.f;
    }
    if (tid < 64) {
        float2 iv = g_inv[n];
        s_sd[tid] = __half2float(g_slt16[n * 128 + tid]) * iv.x;
        s_td[tid] = __half2float(g_slt16[n * 128 + 64 + tid]) * iv.y;
    }
    if (tid < 8) s_den[tid] = 0.f;
    if (tid < 4) s_etw[tid] = etw_tab[tid];
    __syncthreads();

    int h = lane >> 2, q = lane & 3;
    int kb = lane * 16, d0 = q * 16;
    const ull* ASP = (const ull*)s_as + lane * 8;   // 8 packed pairs, loop-invariant
    const ull* SDP = (const ull*)s_sd + q * 8;
    const ull* TDP = (const ull*)s_td + q * 8;

    float dsum = 0.f;
    ull zero2 = pkf2(0.f, 0.f);
    ull accRp[8], accSp[8], accTp[8];
#pragma unroll
    for (int k = 0; k < 8; k++) { accRp[k] = zero2; accSp[k] = zero2; accTp[k] = zero2; }

    // prefetch pipeline
    int i = warp;
    int packed = 0;
    int4 fA = make_int4(0, 0, 0, 0), fB = fA;
    float2 iv = make_float2(0.f, 0.f);
    if (i < cnt) {
        packed = g_ssrc[start + i];
        int s0i = packed & 0xFFFF;
        const int4* fp = (const int4*)(g_fs16 + (size_t)s0i * 512 + kb);
        fA = fp[0]; fB = fp[1];
        iv = g_inv[s0i];
    }

    while (i < cnt) {
        int s = packed & 0xFFFF;
        float etw = s_etw[packed >> 16];

        const int4* sp = (const int4*)(g_slt16 + (size_t)s * 128 + d0);
        int4 s0 = sp[0], s1 = sp[1];
        int4 t0 = sp[8], t1 = sp[9];

        int inext = i + 8;
        int pn = packed;
        int4 nA = fA, nB = fB;
        float2 niv = iv;
        if (inext < cnt) {
            pn = g_ssrc[start + inext];
            int sn_ = pn & 0xFFFF;
            const int4* fpn = (const int4*)(g_fs16 + (size_t)sn_ * 512 + kb);
            nA = fpn[0]; nB = fpn[1];
            niv = g_inv[sn_];
        }

        // convert once to packed f32x2
        const half2* h2a = (const half2*)&fA;
        const half2* h2b = (const half2*)&fB;
        const half2* sh0 = (const half2*)&s0; const half2* sh1 = (const half2*)&s1;
        const half2* th0 = (const half2*)&t0; const half2* th1 = (const half2*)&t1;
        ull fv[8], sv[8], tv[8];
#pragma unroll
        for (int j = 0; j < 4; j++) {
            fv[j]     = h2p(h2a[j]);
            fv[4 + j] = h2p(h2b[j]);
            sv[j]     = h2p(sh0[j]);
            sv[4 + j] = h2p(sh1[j]);
            tv[j]     = h2p(th0[j]);
            tv[4 + j] = h2p(th1[j]);
        }

        // packed dots
        ull pa_ = zero2, pc_ = zero2, pt_ = zero2;
#pragma unroll
        for (int j = 0; j < 8; j++) {
            fma2p(pa_, fv[j], ASP[j]);
            fma2p(pc_, sv[j], SDP[j]);
            fma2p(pt_, tv[j], TDP[j]);
        }
        float ax, ay, cx, cy, tx_, ty_;
        upkf2(pa_, ax, ay);
        upkf2(pc_, cx, cy);
        upkf2(pt_, tx_, ty_);
        float a = ax + ay, cs = cx + cy, ct = tx_ + ty_;

        a  += __shfl_xor_sync(0xffffffffu, a, 1);
        cs += __shfl_xor_sync(0xffffffffu, cs, 1);
        ct += __shfl_xor_sync(0xffffffffu, ct, 1);
        a  += __shfl_xor_sync(0xffffffffu, a, 2);
        cs += __shfl_xor_sync(0xffffffffu, cs, 2);
        ct += __shfl_xor_sync(0xffffffffu, ct, 2);
        cs *= iv.x;
        ct *= iv.y;

        float sim = (TAOV * cs + (1.f - TAOV) * ct + 1.f) * 0.5f;
        float ev = sim * a * etw;
        float ex = __expf(ev);        // |ev| << 88: shift-free softmax is exact
        dsum += ex;

        ull exx = pkf2(ex, ex);
#pragma unroll
        for (int j = 0; j < 8; j++) {
            fma2p(accRp[j], exx, fv[j]);
            fma2p(accSp[j], exx, sv[j]);
            fma2p(accTp[j], exx, tv[j]);
        }

        packed = pn; fA = nA; fB = nB; iv = niv;
        i = inext;
    }

    if (q == 0) atomicAdd(&s_den[h], dsum);
#pragma unroll
    for (int k = 0; k < 8; k++) {
        float x, y;
        upkf2(accRp[k], x, y);
        atomicAdd(&s_accR[kb + 2 * k], x);
        atomicAdd(&s_accR[kb + 2 * k + 1], y);
        upkf2(accSp[k], x, y);
        atomicAdd(&s_accS[kb + 2 * k], x);
        atomicAdd(&s_accS[kb + 2 * k + 1], y);
        upkf2(accTp[k], x, y);
        atomicAdd(&s_accT[kb + 2 * k], x);
        atomicAdd(&s_accT[kb + 2 * k + 1], y);
    }
    __syncthreads();

    if (tid < 64) {
        int d = tid;
        float rsum = 0.f, ssum = 0.f, tsum = 0.f;
#pragma unroll
        for (int hh = 0; hh < 8; hh++) {
            float den = s_den[hh];
            float inv = (den > 0.f) ? (1.f / den) : 0.f;
            float r = s_accR[hh * 64 + d] * inv + g_res[n * 512 + hh * 64 + d];
            rsum += fmaxf(r, 0.f);
            ssum += s_accS[hh * 64 + d] * inv;
            tsum += s_accT[hh * 64 + d] * inv;
        }
        out[n * 64 + d]               = rsum * 0.125f;
        out[NN * 64 + n * 64 + d]     = sloc[n * 64 + d] + ssum * 0.125f;
        out[2 * NN * 64 + n * 64 + d] = topo[n * 64 + d] + tsum * 0.125f;
    }
}

// ------------------- launch: 6 launches, k_gemm in profile slot 4 -------------------
extern "C" void kernel_launch(void* const* d_in, const int* in_sizes, int n_in,
                              void* d_out, int out_size) {
    const float* feat  = (const float*)d_in[0];
    const float* sloc  = (const float*)d_in[1];
    const float* topo  = (const float*)d_in[2];
    const float* Wp    = (const float*)d_in[3];
    const float* Wr    = (const float*)d_in[4];
    const float* Wprob = (const float*)d_in[5];
    const float* etw   = (const float*)d_in[6];
    const int*   src   = (const int*)d_in[7];
    const int*   dst   = (const int*)d_in[8];
    const int*   ef    = (const int*)d_in[9];
    float* out = (float*)d_out;
    int E = in_sizes[7];
    if (E > EMAX) E = EMAX;

    k_zero<<<7, 256>>>();                                           // 1
    k_prep<<<dim3(49, 16, 7), dim3(32, 8)>>>(feat, Wp, Wr, sloc, topo, dst, E); // 2
    k_scan<<<1, 512>>>();                                           // 3
    k_gemm<<<dim3(16, 13), 256>>>();                                // 4  <- ncu target
    k_as<<<912, 256>>>(Wprob, dst, src, ef, E);                     // 5
    k_edge<<<NN, 256>>>(sloc, topo, etw, out);                      // 6
}